// round 2
// baseline (speedup 1.0000x reference)
#include <cuda_runtime.h>
#include <cstdint>

#define IN_DIM 1433
#define HID 16
#define OUTD 7
#define MAXN 200000

// Scratch (no allocations allowed; __device__ globals are the sanctioned path)
__device__ float g_xw1[(size_t)MAXN * HID];   // X @ W1            (12.8 MB)
__device__ float g_h[(size_t)MAXN * HID];     // A @ (X@W1)        (12.8 MB)
__device__ float g_g[(size_t)MAXN * 8];       // relu(h+b1) @ W2, padded to 8 (6.4 MB)
__device__ int   g_idx64;                     // 1 if adj_indices is int64, 0 if int32

// ---------------------------------------------------------------------------
// Detect index width: node ids are in [0, 200000) so if the buffer is int64,
// every high 32-bit word is exactly 0. If it's int32, the "high words" are
// random node ids (P(all zero over 1024 samples) ~ 0).
__global__ void detect_idx_kernel(const unsigned int* __restrict__ adj_words, int n_edges)
{
    if (blockIdx.x == 0 && threadIdx.x == 0) {
        int is64 = 1;
        int samples = n_edges < 1024 ? n_edges : 1024;
        for (int i = 0; i < samples; i++) {
            if (adj_words[2 * i + 1] != 0u) { is64 = 0; break; }
        }
        g_idx64 = is64;
    }
}

__device__ __forceinline__ void load_edge(const void* adj, int e, int n_edges,
                                          int is64, int& r, int& c)
{
    if (is64) {
        const long long* p = (const long long*)adj;
        r = (int)p[e];
        c = (int)p[(size_t)n_edges + e];
    } else {
        const int* p = (const int*)adj;
        r = p[e];
        c = p[(size_t)n_edges + e];
    }
}

// ---------------------------------------------------------------------------
// Zero H scratch and the output buffer (output is poisoned 0xAA by harness).
__global__ void zero_kernel(float* __restrict__ out, int n_out, int n_h)
{
    int i = blockIdx.x * blockDim.x + threadIdx.x;
    if (i < n_h)   g_h[i] = 0.0f;
    if (i < n_out) out[i] = 0.0f;
}

// ---------------------------------------------------------------------------
// GEMM1: XW1[row, 0:16] = feature[row, :] @ W1.  One warp per row; lanes
// split K (coalesced 128B feature reads); W1 (1433x16 f32 = 91.7 KB) staged in
// dynamic shared memory once per 32-row block.
__global__ __launch_bounds__(1024) void gemm1_kernel(
    const float* __restrict__ feature,
    const float* __restrict__ W1,
    int n_nodes)
{
    extern __shared__ float sW1[];   // IN_DIM * HID floats
    for (int i = threadIdx.x; i < IN_DIM * HID; i += blockDim.x)
        sW1[i] = W1[i];
    __syncthreads();

    const int warp = threadIdx.x >> 5;
    const int lane = threadIdx.x & 31;
    const int row  = blockIdx.x * 32 + warp;
    if (row >= n_nodes) return;

    float4 a0 = make_float4(0.f, 0.f, 0.f, 0.f);
    float4 a1 = a0, a2 = a0, a3 = a0;

    const float* frow = feature + (size_t)row * IN_DIM;
    for (int k = lane; k < IN_DIM; k += 32) {
        const float f = frow[k];
        const float4* w = (const float4*)(sW1 + k * HID);
        const float4 w0 = w[0], w1 = w[1], w2 = w[2], w3 = w[3];
        a0.x += f * w0.x; a0.y += f * w0.y; a0.z += f * w0.z; a0.w += f * w0.w;
        a1.x += f * w1.x; a1.y += f * w1.y; a1.z += f * w1.z; a1.w += f * w1.w;
        a2.x += f * w2.x; a2.y += f * w2.y; a2.z += f * w2.z; a2.w += f * w2.w;
        a3.x += f * w3.x; a3.y += f * w3.y; a3.z += f * w3.z; a3.w += f * w3.w;
    }

    #pragma unroll
    for (int off = 16; off; off >>= 1) {
        a0.x += __shfl_xor_sync(0xffffffffu, a0.x, off);
        a0.y += __shfl_xor_sync(0xffffffffu, a0.y, off);
        a0.z += __shfl_xor_sync(0xffffffffu, a0.z, off);
        a0.w += __shfl_xor_sync(0xffffffffu, a0.w, off);
        a1.x += __shfl_xor_sync(0xffffffffu, a1.x, off);
        a1.y += __shfl_xor_sync(0xffffffffu, a1.y, off);
        a1.z += __shfl_xor_sync(0xffffffffu, a1.z, off);
        a1.w += __shfl_xor_sync(0xffffffffu, a1.w, off);
        a2.x += __shfl_xor_sync(0xffffffffu, a2.x, off);
        a2.y += __shfl_xor_sync(0xffffffffu, a2.y, off);
        a2.z += __shfl_xor_sync(0xffffffffu, a2.z, off);
        a2.w += __shfl_xor_sync(0xffffffffu, a2.w, off);
        a3.x += __shfl_xor_sync(0xffffffffu, a3.x, off);
        a3.y += __shfl_xor_sync(0xffffffffu, a3.y, off);
        a3.z += __shfl_xor_sync(0xffffffffu, a3.z, off);
        a3.w += __shfl_xor_sync(0xffffffffu, a3.w, off);
    }

    if (lane == 0) {
        float4* o = (float4*)(g_xw1 + (size_t)row * HID);
        o[0] = a0; o[1] = a1; o[2] = a2; o[3] = a3;
    }
}

// ---------------------------------------------------------------------------
// SpMM1: g_h[row] += val * g_xw1[col]  for every edge. Scalar L2 atomics.
__global__ __launch_bounds__(256) void spmm1_kernel(
    const void* __restrict__ adj,
    const float* __restrict__ vals,
    int n_edges)
{
    int e = blockIdx.x * blockDim.x + threadIdx.x;
    if (e >= n_edges) return;
    const int is64 = g_idx64;
    int r, c;
    load_edge(adj, e, n_edges, is64, r, c);
    const float v = vals[e];

    const float4* x = (const float4*)(g_xw1 + (size_t)c * HID);
    const float4 x0 = x[0], x1 = x[1], x2 = x[2], x3 = x[3];
    float* h = g_h + (size_t)r * HID;
    atomicAdd(h + 0,  v * x0.x);
    atomicAdd(h + 1,  v * x0.y);
    atomicAdd(h + 2,  v * x0.z);
    atomicAdd(h + 3,  v * x0.w);
    atomicAdd(h + 4,  v * x1.x);
    atomicAdd(h + 5,  v * x1.y);
    atomicAdd(h + 6,  v * x1.z);
    atomicAdd(h + 7,  v * x1.w);
    atomicAdd(h + 8,  v * x2.x);
    atomicAdd(h + 9,  v * x2.y);
    atomicAdd(h + 10, v * x2.z);
    atomicAdd(h + 11, v * x2.w);
    atomicAdd(h + 12, v * x3.x);
    atomicAdd(h + 13, v * x3.y);
    atomicAdd(h + 14, v * x3.z);
    atomicAdd(h + 15, v * x3.w);
}

// ---------------------------------------------------------------------------
// GEMM2 (fused bias1 + ReLU): g_g[node, 0:7] = relu(g_h[node]+b1) @ W2, pad [7]=0
__global__ __launch_bounds__(256) void gemm2_kernel(
    const float* __restrict__ b1,
    const float* __restrict__ W2,
    int n_nodes)
{
    __shared__ float sW2[HID * OUTD];
    __shared__ float sb1[HID];
    if (threadIdx.x < HID * OUTD) sW2[threadIdx.x] = W2[threadIdx.x];
    if (threadIdx.x < HID)        sb1[threadIdx.x] = b1[threadIdx.x];
    __syncthreads();

    int i = blockIdx.x * blockDim.x + threadIdx.x;
    if (i >= n_nodes) return;

    float h[HID];
    const float4* hp = (const float4*)(g_h + (size_t)i * HID);
    #pragma unroll
    for (int q = 0; q < 4; q++) {
        float4 a = hp[q];
        h[4 * q + 0] = a.x; h[4 * q + 1] = a.y;
        h[4 * q + 2] = a.z; h[4 * q + 3] = a.w;
    }

    float o[OUTD];
    #pragma unroll
    for (int j = 0; j < OUTD; j++) o[j] = 0.0f;
    #pragma unroll
    for (int k = 0; k < HID; k++) {
        const float hv = fmaxf(h[k] + sb1[k], 0.0f);
        #pragma unroll
        for (int j = 0; j < OUTD; j++) o[j] += hv * sW2[k * OUTD + j];
    }

    float4* g = (float4*)(g_g + (size_t)i * 8);
    g[0] = make_float4(o[0], o[1], o[2], o[3]);
    g[1] = make_float4(o[4], o[5], o[6], 0.0f);
}

// ---------------------------------------------------------------------------
// SpMM2: out[row, 0:7] += val * g_g[col, 0:7]
__global__ __launch_bounds__(256) void spmm2_kernel(
    const void* __restrict__ adj,
    const float* __restrict__ vals,
    float* __restrict__ out,
    int n_edges)
{
    int e = blockIdx.x * blockDim.x + threadIdx.x;
    if (e >= n_edges) return;
    const int is64 = g_idx64;
    int r, c;
    load_edge(adj, e, n_edges, is64, r, c);
    const float v = vals[e];

    const float4* gp = (const float4*)(g_g + (size_t)c * 8);
    const float4 g0 = gp[0], g1 = gp[1];
    float* o = out + (size_t)r * OUTD;
    atomicAdd(o + 0, v * g0.x);
    atomicAdd(o + 1, v * g0.y);
    atomicAdd(o + 2, v * g0.z);
    atomicAdd(o + 3, v * g0.w);
    atomicAdd(o + 4, v * g1.x);
    atomicAdd(o + 5, v * g1.y);
    atomicAdd(o + 6, v * g1.z);
}

// ---------------------------------------------------------------------------
__global__ void bias2_kernel(float* __restrict__ out, const float* __restrict__ b2, int n)
{
    int i = blockIdx.x * blockDim.x + threadIdx.x;
    if (i < n) out[i] += b2[i % OUTD];
}

// ---------------------------------------------------------------------------
extern "C" void kernel_launch(void* const* d_in, const int* in_sizes, int n_in,
                              void* d_out, int out_size)
{
    const void*  adj     = d_in[0];
    const float* vals    = (const float*)d_in[1];
    const float* feature = (const float*)d_in[2];
    const float* W1      = (const float*)d_in[3];
    const float* b1      = (const float*)d_in[4];
    const float* W2      = (const float*)d_in[5];
    const float* b2      = (const float*)d_in[6];
    float*       out     = (float*)d_out;

    const int n_edges = in_sizes[1];
    const int n_nodes = in_sizes[2] / IN_DIM;

    static bool attr_set = false;
    if (!attr_set) {
        cudaFuncSetAttribute(gemm1_kernel,
                             cudaFuncAttributeMaxDynamicSharedMemorySize,
                             IN_DIM * HID * (int)sizeof(float));
        attr_set = true;
    }

    // 1) index-width detection (reads only edge data; deterministic)
    detect_idx_kernel<<<1, 32>>>((const unsigned int*)adj, n_edges);

    // 2) zero H scratch and out
    {
        int n_h = n_nodes * HID;
        int n_max = n_h > out_size ? n_h : out_size;
        zero_kernel<<<(n_max + 255) / 256, 256>>>(out, out_size, n_h);
    }

    // 3) XW1 = feature @ W1
    gemm1_kernel<<<(n_nodes + 31) / 32, 1024, IN_DIM * HID * (int)sizeof(float)>>>(
        feature, W1, n_nodes);

    // 4) H = A @ XW1
    spmm1_kernel<<<(n_edges + 255) / 256, 256>>>(adj, vals, n_edges);

    // 5) G = relu(H + b1) @ W2
    gemm2_kernel<<<(n_nodes + 255) / 256, 256>>>(b1, W2, n_nodes);

    // 6) out = A @ G
    spmm2_kernel<<<(n_edges + 255) / 256, 256>>>(adj, vals, out, n_edges);

    // 7) out += b2
    bias2_kernel<<<(out_size + 255) / 256, 256>>>(out, b2, out_size);
}

// round 3
// speedup vs baseline: 2.8336x; 2.8336x over previous
#include <cuda_runtime.h>
#include <cstdint>

#define IN_DIM 1433
#define HID 16
#define OUTD 7
#define MAXN 200000
#define W1PAD 20   // floats per W1 row in smem (80B stride -> conflict-free LDS.128)

// Scratch (__device__ globals; no allocations allowed)
__device__ float g_xw1[(size_t)MAXN * HID];   // X @ W1                     (12.8 MB)
__device__ float g_h[(size_t)MAXN * HID];     // A @ (X@W1)                 (12.8 MB)
__device__ float g_g[(size_t)MAXN * 8];       // relu(h+b1) @ W2, pad to 8  (6.4 MB)
__device__ float g_out2[(size_t)MAXN * 8];    // A @ G, padded to 8         (6.4 MB)
__device__ int   g_idx64;                     // 1 if adj_indices is int64

// ---------------------------------------------------------------------------
// PTX helpers
__device__ __forceinline__ unsigned long long pack2(float lo, float hi) {
    unsigned long long r;
    asm("mov.b64 %0, {%1, %2};" : "=l"(r) : "f"(lo), "f"(hi));
    return r;
}
__device__ __forceinline__ void unpack2(unsigned long long v, float& lo, float& hi) {
    asm("mov.b64 {%0, %1}, %2;" : "=f"(lo), "=f"(hi) : "l"(v));
}
__device__ __forceinline__ void ffma2(unsigned long long& d,
                                      unsigned long long a, unsigned long long b) {
    asm("fma.rn.f32x2 %0, %1, %2, %0;" : "+l"(d) : "l"(a), "l"(b));
}
__device__ __forceinline__ void red_add_v4(float* addr, float a, float b, float c, float d) {
    asm volatile("red.global.add.v4.f32 [%0], {%1, %2, %3, %4};"
                 :: "l"(addr), "f"(a), "f"(b), "f"(c), "f"(d) : "memory");
}

// ---------------------------------------------------------------------------
// Parallel index-width detection: int64 node ids < 2^31 -> all high words 0.
__global__ void detect_idx_kernel(const unsigned int* __restrict__ adj_words, int n_edges)
{
    int i = threadIdx.x;
    int samples = n_edges < 1024 ? n_edges : 1024;
    int ok = 1;
    if (i < samples) ok = (adj_words[2 * i + 1] == 0u) ? 1 : 0;
    int all = __syncthreads_and(ok);
    if (i == 0) g_idx64 = all;
}

__device__ __forceinline__ void load_edge(const void* adj, int e, int n_edges,
                                          int is64, int& r, int& c)
{
    if (is64) {
        const long long* p = (const long long*)adj;
        r = (int)__ldg(p + e);
        c = (int)__ldg(p + (size_t)n_edges + e);
    } else {
        const int* p = (const int*)adj;
        r = __ldg(p + e);
        c = __ldg(p + (size_t)n_edges + e);
    }
}

// ---------------------------------------------------------------------------
// Zero the two scatter targets.
__global__ void zero_kernel(int n_h, int n_o2)
{
    int i = blockIdx.x * blockDim.x + threadIdx.x;
    if (i < n_h)  g_h[i]    = 0.0f;
    if (i < n_o2) g_out2[i] = 0.0f;
}

// ---------------------------------------------------------------------------
// GEMM1: XW1 = feature @ W1.
// Block = 512 threads = 16 warps; each warp computes 4 rows x 16 cols.
// Lanes split K (coalesced feature loads). W1 staged in smem with pad-20 rows
// (conflict-free LDS.128). Packed f32x2 FMAs halve the FFMA count.
__global__ __launch_bounds__(512, 1) void gemm1_kernel(
    const float* __restrict__ feature,
    const float* __restrict__ W1,
    int n_nodes)
{
    extern __shared__ float sW1[];   // IN_DIM * W1PAD floats
    for (int i = threadIdx.x; i < IN_DIM * HID; i += 512) {
        int k = i >> 4, j = i & 15;
        sW1[k * W1PAD + j] = W1[i];
    }
    __syncthreads();

    const int warp = threadIdx.x >> 5;
    const int lane = threadIdx.x & 31;
    const int row0 = blockIdx.x * 64 + warp * 4;

    unsigned long long acc[4][8];
    #pragma unroll
    for (int r = 0; r < 4; r++)
        #pragma unroll
        for (int j = 0; j < 8; j++) acc[r][j] = 0ull;

    for (int kb = 0; kb < IN_DIM; kb += 32) {
        const int k = kb + lane;
        const bool kvalid = (k < IN_DIM);
        const int ke = kvalid ? k : 0;

        float f[4];
        #pragma unroll
        for (int r = 0; r < 4; r++) {
            int row = row0 + r;
            f[r] = (kvalid && row < n_nodes) ? __ldg(feature + (size_t)row * IN_DIM + k)
                                             : 0.0f;
        }

        const float4* wp = (const float4*)(sW1 + ke * W1PAD);  // 80B stride, 16B aligned
        const float4 w0 = wp[0], w1 = wp[1], w2 = wp[2], w3 = wp[3];
        unsigned long long wq[8];
        wq[0] = pack2(w0.x, w0.y); wq[1] = pack2(w0.z, w0.w);
        wq[2] = pack2(w1.x, w1.y); wq[3] = pack2(w1.z, w1.w);
        wq[4] = pack2(w2.x, w2.y); wq[5] = pack2(w2.z, w2.w);
        wq[6] = pack2(w3.x, w3.y); wq[7] = pack2(w3.z, w3.w);

        #pragma unroll
        for (int r = 0; r < 4; r++) {
            const unsigned long long fr = pack2(f[r], f[r]);
            #pragma unroll
            for (int j = 0; j < 8; j++) ffma2(acc[r][j], fr, wq[j]);
        }
    }

    // Warp reduction: 16 outputs per row, accumulated as 8 f32x2 per lane.
    #pragma unroll
    for (int r = 0; r < 4; r++) {
        int row = row0 + r;
        #pragma unroll
        for (int j = 0; j < 8; j++) {
            float lo, hi;
            unpack2(acc[r][j], lo, hi);
            #pragma unroll
            for (int off = 16; off; off >>= 1) {
                lo += __shfl_xor_sync(0xffffffffu, lo, off);
                hi += __shfl_xor_sync(0xffffffffu, hi, off);
            }
            if (lane == 0 && row < n_nodes)
                ((unsigned long long*)(g_xw1 + (size_t)row * HID))[j] = pack2(lo, hi);
        }
    }
}

// ---------------------------------------------------------------------------
// SpMM1: g_h[row] += val * g_xw1[col].  4x red.global.add.v4.f32 per edge.
__global__ __launch_bounds__(256) void spmm1_kernel(
    const void* __restrict__ adj,
    const float* __restrict__ vals,
    int n_edges)
{
    int e = blockIdx.x * blockDim.x + threadIdx.x;
    if (e >= n_edges) return;
    const int is64 = g_idx64;
    int r, c;
    load_edge(adj, e, n_edges, is64, r, c);
    const float v = __ldg(vals + e);

    const float4* x = (const float4*)(g_xw1 + (size_t)c * HID);
    const float4 x0 = __ldg(x + 0), x1 = __ldg(x + 1),
                 x2 = __ldg(x + 2), x3 = __ldg(x + 3);
    float* h = g_h + (size_t)r * HID;
    red_add_v4(h + 0,  v * x0.x, v * x0.y, v * x0.z, v * x0.w);
    red_add_v4(h + 4,  v * x1.x, v * x1.y, v * x1.z, v * x1.w);
    red_add_v4(h + 8,  v * x2.x, v * x2.y, v * x2.z, v * x2.w);
    red_add_v4(h + 12, v * x3.x, v * x3.y, v * x3.z, v * x3.w);
}

// ---------------------------------------------------------------------------
// GEMM2 (fused bias1 + ReLU): g_g[node, 0:7] = relu(g_h[node]+b1) @ W2, pad [7]=0
__global__ __launch_bounds__(256) void gemm2_kernel(
    const float* __restrict__ b1,
    const float* __restrict__ W2,
    int n_nodes)
{
    __shared__ float sW2[HID * OUTD];
    __shared__ float sb1[HID];
    if (threadIdx.x < HID * OUTD) sW2[threadIdx.x] = W2[threadIdx.x];
    if (threadIdx.x < HID)        sb1[threadIdx.x] = b1[threadIdx.x];
    __syncthreads();

    int i = blockIdx.x * blockDim.x + threadIdx.x;
    if (i >= n_nodes) return;

    float h[HID];
    const float4* hp = (const float4*)(g_h + (size_t)i * HID);
    #pragma unroll
    for (int q = 0; q < 4; q++) {
        float4 a = hp[q];
        h[4 * q + 0] = a.x; h[4 * q + 1] = a.y;
        h[4 * q + 2] = a.z; h[4 * q + 3] = a.w;
    }

    float o[OUTD];
    #pragma unroll
    for (int j = 0; j < OUTD; j++) o[j] = 0.0f;
    #pragma unroll
    for (int k = 0; k < HID; k++) {
        const float hv = fmaxf(h[k] + sb1[k], 0.0f);
        #pragma unroll
        for (int j = 0; j < OUTD; j++) o[j] += hv * sW2[k * OUTD + j];
    }

    float4* g = (float4*)(g_g + (size_t)i * 8);
    g[0] = make_float4(o[0], o[1], o[2], o[3]);
    g[1] = make_float4(o[4], o[5], o[6], 0.0f);   // pad slot stays 0
}

// ---------------------------------------------------------------------------
// SpMM2: g_out2[row, 0:8] += val * g_g[col, 0:8].  2x v4 REDs (pad gets +0).
__global__ __launch_bounds__(256) void spmm2_kernel(
    const void* __restrict__ adj,
    const float* __restrict__ vals,
    int n_edges)
{
    int e = blockIdx.x * blockDim.x + threadIdx.x;
    if (e >= n_edges) return;
    const int is64 = g_idx64;
    int r, c;
    load_edge(adj, e, n_edges, is64, r, c);
    const float v = __ldg(vals + e);

    const float4* gp = (const float4*)(g_g + (size_t)c * 8);
    const float4 g0 = __ldg(gp + 0), g1 = __ldg(gp + 1);
    float* o = g_out2 + (size_t)r * 8;
    red_add_v4(o + 0, v * g0.x, v * g0.y, v * g0.z, v * g0.w);
    red_add_v4(o + 4, v * g1.x, v * g1.y, v * g1.z, v * g1.w);  // last lane: v*0
}

// ---------------------------------------------------------------------------
// Finalize: out[i,j] = g_out2[i, j(<7)] + b2[j]   (compact 8->7 + bias)
__global__ void finalize_kernel(float* __restrict__ out,
                                const float* __restrict__ b2, int n_total)
{
    int i = blockIdx.x * blockDim.x + threadIdx.x;
    if (i < n_total) {
        int r = i / OUTD, j = i - r * OUTD;
        out[i] = g_out2[(size_t)r * 8 + j] + __ldg(b2 + j);
    }
}

// ---------------------------------------------------------------------------
extern "C" void kernel_launch(void* const* d_in, const int* in_sizes, int n_in,
                              void* d_out, int out_size)
{
    const void*  adj     = d_in[0];
    const float* vals    = (const float*)d_in[1];
    const float* feature = (const float*)d_in[2];
    const float* W1      = (const float*)d_in[3];
    const float* b1      = (const float*)d_in[4];
    const float* W2      = (const float*)d_in[5];
    const float* b2      = (const float*)d_in[6];
    float*       out     = (float*)d_out;

    const int n_edges = in_sizes[1];
    const int n_nodes = in_sizes[2] / IN_DIM;
    const int smem1   = IN_DIM * W1PAD * (int)sizeof(float);  // ~114.6 KB

    static bool attr_set = false;
    if (!attr_set) {
        cudaFuncSetAttribute(gemm1_kernel,
                             cudaFuncAttributeMaxDynamicSharedMemorySize, smem1);
        attr_set = true;
    }

    // 1) index-width detection (parallel)
    detect_idx_kernel<<<1, 1024>>>((const unsigned int*)adj, n_edges);

    // 2) zero scatter targets
    {
        int n_h  = n_nodes * HID;
        int n_o2 = n_nodes * 8;
        zero_kernel<<<(n_h + 255) / 256, 256>>>(n_h, n_o2);
    }

    // 3) XW1 = feature @ W1
    gemm1_kernel<<<(n_nodes + 63) / 64, 512, smem1>>>(feature, W1, n_nodes);

    // 4) H = A @ XW1
    spmm1_kernel<<<(n_edges + 255) / 256, 256>>>(adj, vals, n_edges);

    // 5) G = relu(H + b1) @ W2
    gemm2_kernel<<<(n_nodes + 255) / 256, 256>>>(b1, W2, n_nodes);

    // 6) OUT2 = A @ G (padded)
    spmm2_kernel<<<(n_edges + 255) / 256, 256>>>(adj, vals, n_edges);

    // 7) out = compact(OUT2) + b2
    finalize_kernel<<<(out_size + 255) / 256, 256>>>(out, b2, out_size);
}

// round 4
// speedup vs baseline: 3.5450x; 1.2511x over previous
#include <cuda_runtime.h>
#include <cstdint>

#define IN_DIM 1433
#define HID 16
#define OUTD 7
#define MAXN 200000
#define MAXE 6400000
#define MAXNB 256          // max scan blocks: ceil(200000/1024)=196
#define W1PAD 20           // 80B row stride -> conflict-free LDS.128

// Scratch (__device__ globals; allocations are forbidden)
__device__ float g_xw1[(size_t)MAXN * HID];     // X @ W1                (12.8 MB)
__device__ float g_h[(size_t)MAXN * HID];       // A @ XW1               (12.8 MB)
__device__ float g_g[(size_t)MAXN * 8];         // relu(H+b1)@W2 pad8    ( 6.4 MB)
__device__ int2  g_csr[(size_t)MAXE];           // (col, val-bits)       (51.2 MB)
__device__ int   g_rowcnt[MAXN];
__device__ int   g_rowfill[MAXN];
__device__ int   g_rowptr[MAXN + 1];
__device__ int   g_blocksum[MAXNB];
__device__ int   g_blockoff[MAXNB];
__device__ int   g_idx64;

// ---------------------------------------------------------------------------
// PTX helpers
__device__ __forceinline__ unsigned long long pack2(float lo, float hi) {
    unsigned long long r;
    asm("mov.b64 %0, {%1, %2};" : "=l"(r) : "f"(lo), "f"(hi));
    return r;
}
__device__ __forceinline__ void unpack2(unsigned long long v, float& lo, float& hi) {
    asm("mov.b64 {%0, %1}, %2;" : "=f"(lo), "=f"(hi) : "l"(v));
}
__device__ __forceinline__ void ffma2(unsigned long long& d,
                                      unsigned long long a, unsigned long long b) {
    asm("fma.rn.f32x2 %0, %1, %2, %0;" : "+l"(d) : "l"(a), "l"(b));
}

// ---------------------------------------------------------------------------
// Index-width detection (int64 ids < 2^31 -> high words all zero).
__global__ void detect_idx_kernel(const unsigned int* __restrict__ adj_words, int n_edges)
{
    int i = threadIdx.x;
    int samples = n_edges < 1024 ? n_edges : 1024;
    int ok = 1;
    if (i < samples) ok = (adj_words[2 * i + 1] == 0u) ? 1 : 0;
    int all = __syncthreads_and(ok);
    if (i == 0) g_idx64 = all;
}

__device__ __forceinline__ int load_row(const void* adj, int e, int is64) {
    return is64 ? (int)__ldg((const long long*)adj + e)
                : __ldg((const int*)adj + e);
}
__device__ __forceinline__ int load_col(const void* adj, int e, int n_edges, int is64) {
    return is64 ? (int)__ldg((const long long*)adj + (size_t)n_edges + e)
                : __ldg((const int*)adj + (size_t)n_edges + e);
}

// ---------------------------------------------------------------------------
__global__ void zero_counts_kernel(int n)
{
    int i = blockIdx.x * blockDim.x + threadIdx.x;
    if (i < n) { g_rowcnt[i] = 0; g_rowfill[i] = 0; }
}

// ---------------------------------------------------------------------------
// CSR build: histogram -> 2-level exclusive scan -> scatter.
__global__ __launch_bounds__(256) void histogram_kernel(
    const void* __restrict__ adj, int n_edges)
{
    int e = blockIdx.x * blockDim.x + threadIdx.x;
    if (e >= n_edges) return;
    int r = load_row(adj, e, g_idx64);
    atomicAdd(&g_rowcnt[r], 1);
}

__device__ __forceinline__ int block_excl_scan(int v, int* warp_sums, int nwarps)
{
    const int lane = threadIdx.x & 31, w = threadIdx.x >> 5;
    int x = v;
    #pragma unroll
    for (int off = 1; off < 32; off <<= 1) {
        int y = __shfl_up_sync(0xffffffffu, x, off);
        if (lane >= off) x += y;
    }
    if (lane == 31) warp_sums[w] = x;
    __syncthreads();
    if (w == 0) {
        int s = (lane < nwarps) ? warp_sums[lane] : 0;
        #pragma unroll
        for (int off = 1; off < 32; off <<= 1) {
            int y = __shfl_up_sync(0xffffffffu, s, off);
            if (lane >= off) s += y;
        }
        if (lane < nwarps) warp_sums[lane] = s;   // inclusive warp totals
    }
    __syncthreads();
    int base = (w > 0) ? warp_sums[w - 1] : 0;
    return base + x - v;                          // exclusive
}

__global__ __launch_bounds__(1024) void scan1_kernel(int n)
{
    __shared__ int ws[32];
    int i = blockIdx.x * 1024 + threadIdx.x;
    int v = (i < n) ? g_rowcnt[i] : 0;
    int ex = block_excl_scan(v, ws, 32);
    if (threadIdx.x == 1023) g_blocksum[blockIdx.x] = ex + v;
}

__global__ __launch_bounds__(256) void scan2_kernel(int nb)
{
    __shared__ int ws[32];
    int i = threadIdx.x;
    int v = (i < nb) ? g_blocksum[i] : 0;
    int ex = block_excl_scan(v, ws, 8);
    if (i < nb) g_blockoff[i] = ex;
}

__global__ __launch_bounds__(1024) void scan3_kernel(int n)
{
    __shared__ int ws[32];
    int i = blockIdx.x * 1024 + threadIdx.x;
    int v = (i < n) ? g_rowcnt[i] : 0;
    int ex = block_excl_scan(v, ws, 32);
    int base = g_blockoff[blockIdx.x];
    if (i < n)     g_rowptr[i] = base + ex;
    if (i == n - 1) g_rowptr[n] = base + ex + v;
}

__global__ __launch_bounds__(256) void scatter_kernel(
    const void* __restrict__ adj, const float* __restrict__ vals, int n_edges)
{
    int e = blockIdx.x * blockDim.x + threadIdx.x;
    if (e >= n_edges) return;
    const int is64 = g_idx64;
    int r = load_row(adj, e, is64);
    int c = load_col(adj, e, n_edges, is64);
    float v = __ldg(vals + e);
    int pos = g_rowptr[r] + atomicAdd(&g_rowfill[r], 1);
    g_csr[pos] = make_int2(c, __float_as_int(v));
}

// ---------------------------------------------------------------------------
// GEMM1: XW1 = feature @ W1.  512 thr = 16 warps x 4 rows; lanes split K.
// k-loop unrolled x2 => 8 DRAM loads in flight per warp-iter (MLP 8).
// W1 in smem, pad-20 rows (conflict-free LDS.128). f32x2 packed FMAs.
__global__ __launch_bounds__(512, 1) void gemm1_kernel(
    const float* __restrict__ feature,
    const float* __restrict__ W1,
    int n_nodes)
{
    extern __shared__ float sW1[];   // IN_DIM * W1PAD
    for (int i = threadIdx.x; i < IN_DIM * HID; i += 512) {
        int k = i >> 4, j = i & 15;
        sW1[k * W1PAD + j] = W1[i];
    }
    __syncthreads();

    const int warp = threadIdx.x >> 5;
    const int lane = threadIdx.x & 31;
    const int row0 = blockIdx.x * 64 + warp * 4;

    unsigned long long acc[4][8];
    #pragma unroll
    for (int r = 0; r < 4; r++)
        #pragma unroll
        for (int j = 0; j < 8; j++) acc[r][j] = 0ull;

    for (int kb = 0; kb < IN_DIM; kb += 64) {
        const int k0 = kb + lane, k1 = k0 + 32;
        const bool v0 = (k0 < IN_DIM), v1 = (k1 < IN_DIM);
        const int ke0 = v0 ? k0 : 0, ke1 = v1 ? k1 : 0;

        float f0[4], f1[4];
        #pragma unroll
        for (int r = 0; r < 4; r++) {
            const int row = row0 + r;
            const bool rv = (row < n_nodes);
            const float* fr = feature + (size_t)row * IN_DIM;
            f0[r] = (v0 && rv) ? __ldg(fr + k0) : 0.0f;
            f1[r] = (v1 && rv) ? __ldg(fr + k1) : 0.0f;
        }

        {   // k0 slice
            const float4* wp = (const float4*)(sW1 + ke0 * W1PAD);
            const float4 w0 = wp[0], w1 = wp[1], w2 = wp[2], w3 = wp[3];
            unsigned long long wq[8];
            wq[0] = pack2(w0.x, w0.y); wq[1] = pack2(w0.z, w0.w);
            wq[2] = pack2(w1.x, w1.y); wq[3] = pack2(w1.z, w1.w);
            wq[4] = pack2(w2.x, w2.y); wq[5] = pack2(w2.z, w2.w);
            wq[6] = pack2(w3.x, w3.y); wq[7] = pack2(w3.z, w3.w);
            #pragma unroll
            for (int r = 0; r < 4; r++) {
                const unsigned long long fr2 = pack2(f0[r], f0[r]);
                #pragma unroll
                for (int j = 0; j < 8; j++) ffma2(acc[r][j], fr2, wq[j]);
            }
        }
        {   // k1 slice
            const float4* wp = (const float4*)(sW1 + ke1 * W1PAD);
            const float4 w0 = wp[0], w1 = wp[1], w2 = wp[2], w3 = wp[3];
            unsigned long long wq[8];
            wq[0] = pack2(w0.x, w0.y); wq[1] = pack2(w0.z, w0.w);
            wq[2] = pack2(w1.x, w1.y); wq[3] = pack2(w1.z, w1.w);
            wq[4] = pack2(w2.x, w2.y); wq[5] = pack2(w2.z, w2.w);
            wq[6] = pack2(w3.x, w3.y); wq[7] = pack2(w3.z, w3.w);
            #pragma unroll
            for (int r = 0; r < 4; r++) {
                const unsigned long long fr2 = pack2(f1[r], f1[r]);
                #pragma unroll
                for (int j = 0; j < 8; j++) ffma2(acc[r][j], fr2, wq[j]);
            }
        }
    }

    #pragma unroll
    for (int r = 0; r < 4; r++) {
        const int row = row0 + r;
        #pragma unroll
        for (int j = 0; j < 8; j++) {
            float lo, hi;
            unpack2(acc[r][j], lo, hi);
            #pragma unroll
            for (int off = 16; off; off >>= 1) {
                lo += __shfl_xor_sync(0xffffffffu, lo, off);
                hi += __shfl_xor_sync(0xffffffffu, hi, off);
            }
            if (lane == 0 && row < n_nodes)
                ((unsigned long long*)(g_xw1 + (size_t)row * HID))[j] = pack2(lo, hi);
        }
    }
}

// ---------------------------------------------------------------------------
// Gather SpMM1: warp per row, half-warp (16 lanes) per edge, D=16.
// g_h[row][j] = sum_e val_e * g_xw1[col_e][j].  No atomics.
__global__ __launch_bounds__(256) void spmm1_gather_kernel(int n_nodes)
{
    const int warp_id = (blockIdx.x * blockDim.x + threadIdx.x) >> 5;
    if (warp_id >= n_nodes) return;
    const int lane = threadIdx.x & 31;
    const int half = lane >> 4;      // 0/1 -> which edge of the pair
    const int j    = lane & 15;      // feature index

    const int start = g_rowptr[warp_id];
    const int end   = g_rowptr[warp_id + 1];

    float acc = 0.0f;
    #pragma unroll 2
    for (int e = start + half; e < end; e += 2) {
        const int2 ev = __ldg(&g_csr[e]);
        acc += __int_as_float(ev.y) * __ldg(g_xw1 + (size_t)ev.x * HID + j);
    }
    acc += __shfl_xor_sync(0xffffffffu, acc, 16);
    if (half == 0)
        g_h[(size_t)warp_id * HID + j] = acc;   // 16 lanes -> 64B coalesced
}

// ---------------------------------------------------------------------------
// GEMM2 (bias1 + ReLU fused): g_g[i, 0:7] = relu(g_h[i]+b1) @ W2, pad [7]=0
__global__ __launch_bounds__(256) void gemm2_kernel(
    const float* __restrict__ b1,
    const float* __restrict__ W2,
    int n_nodes)
{
    __shared__ float sW2[HID * OUTD];
    __shared__ float sb1[HID];
    if (threadIdx.x < HID * OUTD) sW2[threadIdx.x] = W2[threadIdx.x];
    if (threadIdx.x < HID)        sb1[threadIdx.x] = b1[threadIdx.x];
    __syncthreads();

    int i = blockIdx.x * blockDim.x + threadIdx.x;
    if (i >= n_nodes) return;

    float h[HID];
    const float4* hp = (const float4*)(g_h + (size_t)i * HID);
    #pragma unroll
    for (int q = 0; q < 4; q++) {
        float4 a = hp[q];
        h[4 * q + 0] = a.x; h[4 * q + 1] = a.y;
        h[4 * q + 2] = a.z; h[4 * q + 3] = a.w;
    }

    float o[OUTD];
    #pragma unroll
    for (int j = 0; j < OUTD; j++) o[j] = 0.0f;
    #pragma unroll
    for (int k = 0; k < HID; k++) {
        const float hv = fmaxf(h[k] + sb1[k], 0.0f);
        #pragma unroll
        for (int j = 0; j < OUTD; j++) o[j] += hv * sW2[k * OUTD + j];
    }

    float4* g = (float4*)(g_g + (size_t)i * 8);
    g[0] = make_float4(o[0], o[1], o[2], o[3]);
    g[1] = make_float4(o[4], o[5], o[6], 0.0f);
}

// ---------------------------------------------------------------------------
// Gather SpMM2: warp per row, quarter-warp (8 lanes) per edge, D=8(pad).
// Writes the final output directly with b2 fused. No atomics, no finalize.
__global__ __launch_bounds__(256) void spmm2_gather_kernel(
    float* __restrict__ out, const float* __restrict__ b2, int n_nodes)
{
    const int warp_id = (blockIdx.x * blockDim.x + threadIdx.x) >> 5;
    if (warp_id >= n_nodes) return;
    const int lane = threadIdx.x & 31;
    const int q = lane >> 3;         // 0..3 -> which edge of the quad
    const int j = lane & 7;          // output index (7 used + 1 pad)

    const int start = g_rowptr[warp_id];
    const int end   = g_rowptr[warp_id + 1];

    float acc = 0.0f;
    #pragma unroll 2
    for (int e = start + q; e < end; e += 4) {
        const int2 ev = __ldg(&g_csr[e]);
        acc += __int_as_float(ev.y) * __ldg(g_g + (size_t)ev.x * 8 + j);
    }
    acc += __shfl_xor_sync(0xffffffffu, acc, 16);
    acc += __shfl_xor_sync(0xffffffffu, acc, 8);
    if (lane < OUTD)
        out[(size_t)warp_id * OUTD + j] = acc + __ldg(b2 + j);
}

// ---------------------------------------------------------------------------
extern "C" void kernel_launch(void* const* d_in, const int* in_sizes, int n_in,
                              void* d_out, int out_size)
{
    const void*  adj     = d_in[0];
    const float* vals    = (const float*)d_in[1];
    const float* feature = (const float*)d_in[2];
    const float* W1      = (const float*)d_in[3];
    const float* b1      = (const float*)d_in[4];
    const float* W2      = (const float*)d_in[5];
    const float* b2      = (const float*)d_in[6];
    float*       out     = (float*)d_out;

    const int n_edges = in_sizes[1];
    const int n_nodes = in_sizes[2] / IN_DIM;
    const int nb      = (n_nodes + 1023) / 1024;
    const int smem1   = IN_DIM * W1PAD * (int)sizeof(float);  // ~114.6 KB

    static bool attr_set = false;
    if (!attr_set) {
        cudaFuncSetAttribute(gemm1_kernel,
                             cudaFuncAttributeMaxDynamicSharedMemorySize, smem1);
        attr_set = true;
    }

    // index-width detection + counter reset
    detect_idx_kernel<<<1, 1024>>>((const unsigned int*)adj, n_edges);
    zero_counts_kernel<<<nb, 1024>>>(n_nodes);

    // dense layer 1 (independent of CSR build)
    gemm1_kernel<<<(n_nodes + 63) / 64, 512, smem1>>>(feature, W1, n_nodes);

    // CSR build
    histogram_kernel<<<(n_edges + 255) / 256, 256>>>(adj, n_edges);
    scan1_kernel<<<nb, 1024>>>(n_nodes);
    scan2_kernel<<<1, 256>>>(nb);
    scan3_kernel<<<nb, 1024>>>(n_nodes);
    scatter_kernel<<<(n_edges + 255) / 256, 256>>>(adj, vals, n_edges);

    // H = A @ XW1 (gather, no atomics)
    spmm1_gather_kernel<<<(n_nodes * 32 + 255) / 256, 256>>>(n_nodes);

    // G = relu(H + b1) @ W2
    gemm2_kernel<<<(n_nodes + 255) / 256, 256>>>(b1, W2, n_nodes);

    // out = A @ G + b2 (gather, direct write)
    spmm2_gather_kernel<<<(n_nodes * 32 + 255) / 256, 256>>>(out, b2, n_nodes);
}

// round 5
// speedup vs baseline: 4.1485x; 1.1702x over previous
#include <cuda_runtime.h>
#include <cstdint>

#define IN_DIM 1433
#define HID 16
#define OUTD 7
#define MAXN 200000
#define MAXE 6400000
#define MAXNB 256
#define W1PAD 20           // 80B row stride -> conflict-free LDS.128

// Scratch (__device__ globals; allocations are forbidden)
__device__ float g_xw1[(size_t)MAXN * HID];     // X @ W1                (12.8 MB)
__device__ float g_h[(size_t)MAXN * HID];       // A @ XW1               (12.8 MB)
__device__ float g_g[(size_t)MAXN * 8];         // relu(H+b1)@W2 pad8    ( 6.4 MB)
__device__ int2  g_csr[(size_t)MAXE];           // (col, val-bits)       (51.2 MB)
__device__ int   g_rowcnt[MAXN];
__device__ int   g_rowfill[MAXN];
__device__ int   g_rowptr[MAXN + 1];
__device__ int   g_blocksum[MAXNB];
__device__ int   g_blockoff[MAXNB];
__device__ int   g_idx64;

// ---------------------------------------------------------------------------
__device__ __forceinline__ unsigned long long pack2(float lo, float hi) {
    unsigned long long r;
    asm("mov.b64 %0, {%1, %2};" : "=l"(r) : "f"(lo), "f"(hi));
    return r;
}
__device__ __forceinline__ void unpack2(unsigned long long v, float& lo, float& hi) {
    asm("mov.b64 {%0, %1}, %2;" : "=f"(lo), "=f"(hi) : "l"(v));
}
__device__ __forceinline__ void ffma2(unsigned long long& d,
                                      unsigned long long a, unsigned long long b) {
    asm("fma.rn.f32x2 %0, %1, %2, %0;" : "+l"(d) : "l"(a), "l"(b));
}

// ---------------------------------------------------------------------------
__global__ void detect_idx_kernel(const unsigned int* __restrict__ adj_words, int n_edges)
{
    int i = threadIdx.x;
    int samples = n_edges < 1024 ? n_edges : 1024;
    int ok = 1;
    if (i < samples) ok = (adj_words[2 * i + 1] == 0u) ? 1 : 0;
    int all = __syncthreads_and(ok);
    if (i == 0) g_idx64 = all;
}

__device__ __forceinline__ int load_row(const void* adj, int e, int is64) {
    return is64 ? (int)__ldg((const long long*)adj + e)
                : __ldg((const int*)adj + e);
}
__device__ __forceinline__ int load_col(const void* adj, int e, int n_edges, int is64) {
    return is64 ? (int)__ldg((const long long*)adj + (size_t)n_edges + e)
                : __ldg((const int*)adj + (size_t)n_edges + e);
}

// ---------------------------------------------------------------------------
__global__ void zero_counts_kernel(int n)
{
    int i = blockIdx.x * blockDim.x + threadIdx.x;
    if (i < n) { g_rowcnt[i] = 0; g_rowfill[i] = 0; }
}

// ---------------------------------------------------------------------------
// CSR build
__global__ __launch_bounds__(256) void histogram_kernel(
    const void* __restrict__ adj, int n_edges)
{
    int e = blockIdx.x * blockDim.x + threadIdx.x;
    if (e >= n_edges) return;
    int r = load_row(adj, e, g_idx64);
    atomicAdd(&g_rowcnt[r], 1);
}

__device__ __forceinline__ int block_excl_scan(int v, int* warp_sums, int nwarps)
{
    const int lane = threadIdx.x & 31, w = threadIdx.x >> 5;
    int x = v;
    #pragma unroll
    for (int off = 1; off < 32; off <<= 1) {
        int y = __shfl_up_sync(0xffffffffu, x, off);
        if (lane >= off) x += y;
    }
    if (lane == 31) warp_sums[w] = x;
    __syncthreads();
    if (w == 0) {
        int s = (lane < nwarps) ? warp_sums[lane] : 0;
        #pragma unroll
        for (int off = 1; off < 32; off <<= 1) {
            int y = __shfl_up_sync(0xffffffffu, s, off);
            if (lane >= off) s += y;
        }
        if (lane < nwarps) warp_sums[lane] = s;
    }
    __syncthreads();
    int base = (w > 0) ? warp_sums[w - 1] : 0;
    return base + x - v;
}

__global__ __launch_bounds__(1024) void scan1_kernel(int n)
{
    __shared__ int ws[32];
    int i = blockIdx.x * 1024 + threadIdx.x;
    int v = (i < n) ? g_rowcnt[i] : 0;
    int ex = block_excl_scan(v, ws, 32);
    if (threadIdx.x == 1023) g_blocksum[blockIdx.x] = ex + v;
}

__global__ __launch_bounds__(256) void scan2_kernel(int nb)
{
    __shared__ int ws[32];
    int i = threadIdx.x;
    int v = (i < nb) ? g_blocksum[i] : 0;
    int ex = block_excl_scan(v, ws, 8);
    if (i < nb) g_blockoff[i] = ex;
}

__global__ __launch_bounds__(1024) void scan3_kernel(int n)
{
    __shared__ int ws[32];
    int i = blockIdx.x * 1024 + threadIdx.x;
    int v = (i < n) ? g_rowcnt[i] : 0;
    int ex = block_excl_scan(v, ws, 32);
    int base = g_blockoff[blockIdx.x];
    if (i < n)      g_rowptr[i] = base + ex;
    if (i == n - 1) g_rowptr[n] = base + ex + v;
}

__global__ __launch_bounds__(256) void scatter_kernel(
    const void* __restrict__ adj, const float* __restrict__ vals, int n_edges)
{
    int e = blockIdx.x * blockDim.x + threadIdx.x;
    if (e >= n_edges) return;
    const int is64 = g_idx64;
    int r = load_row(adj, e, is64);
    int c = load_col(adj, e, n_edges, is64);
    float v = __ldg(vals + e);
    int pos = g_rowptr[r] + atomicAdd(&g_rowfill[r], 1);
    g_csr[pos] = make_int2(c, __float_as_int(v));
}

// ---------------------------------------------------------------------------
// GEMM1: XW1 = feature @ W1.  512 thr = 16 warps x 4 rows; lanes split K.
// k-loop unrolled x4: 16 DRAM loads batched per warp-iter (32KB/SM in flight).
__global__ __launch_bounds__(512, 1) void gemm1_kernel(
    const float* __restrict__ feature,
    const float* __restrict__ W1,
    int n_nodes)
{
    extern __shared__ float sW1[];   // IN_DIM * W1PAD
    for (int i = threadIdx.x; i < IN_DIM * HID; i += 512) {
        int k = i >> 4, j = i & 15;
        sW1[k * W1PAD + j] = W1[i];
    }
    __syncthreads();

    const int warp = threadIdx.x >> 5;
    const int lane = threadIdx.x & 31;
    const int row0 = blockIdx.x * 64 + warp * 4;
    const bool rowsok = (row0 + 3 < n_nodes);

    unsigned long long acc[4][8];
    #pragma unroll
    for (int r = 0; r < 4; r++)
        #pragma unroll
        for (int j = 0; j < 8; j++) acc[r][j] = 0ull;

    for (int kb = 0; kb < IN_DIM; kb += 128) {
        int  kk[4];
        bool kv[4];
        #pragma unroll
        for (int s = 0; s < 4; s++) {
            int k = kb + s * 32 + lane;
            kv[s] = (k < IN_DIM);
            kk[s] = kv[s] ? k : 0;
        }

        // Batch all 16 global loads first (MLP 16 per warp).
        float f[4][4];
        if (rowsok && kb + 127 < IN_DIM) {
            #pragma unroll
            for (int r = 0; r < 4; r++) {
                const float* fr = feature + (size_t)(row0 + r) * IN_DIM + lane + kb;
                #pragma unroll
                for (int s = 0; s < 4; s++) f[r][s] = __ldg(fr + s * 32);
            }
        } else {
            #pragma unroll
            for (int r = 0; r < 4; r++) {
                const bool rv = (row0 + r < n_nodes);
                const float* fr = feature + (size_t)(row0 + r) * IN_DIM;
                #pragma unroll
                for (int s = 0; s < 4; s++)
                    f[r][s] = (rv && kv[s]) ? __ldg(fr + kb + s * 32 + lane) : 0.0f;
            }
        }

        #pragma unroll
        for (int s = 0; s < 4; s++) {
            const float4* wp = (const float4*)(sW1 + kk[s] * W1PAD);
            const float4 w0 = wp[0], w1 = wp[1], w2 = wp[2], w3 = wp[3];
            unsigned long long wq[8];
            wq[0] = pack2(w0.x, w0.y); wq[1] = pack2(w0.z, w0.w);
            wq[2] = pack2(w1.x, w1.y); wq[3] = pack2(w1.z, w1.w);
            wq[4] = pack2(w2.x, w2.y); wq[5] = pack2(w2.z, w2.w);
            wq[6] = pack2(w3.x, w3.y); wq[7] = pack2(w3.z, w3.w);
            #pragma unroll
            for (int r = 0; r < 4; r++) {
                const unsigned long long fr2 = pack2(f[r][s], f[r][s]);
                #pragma unroll
                for (int j = 0; j < 8; j++) ffma2(acc[r][j], fr2, wq[j]);
            }
        }
    }

    #pragma unroll
    for (int r = 0; r < 4; r++) {
        const int row = row0 + r;
        #pragma unroll
        for (int j = 0; j < 8; j++) {
            float lo, hi;
            unpack2(acc[r][j], lo, hi);
            #pragma unroll
            for (int off = 16; off; off >>= 1) {
                lo += __shfl_xor_sync(0xffffffffu, lo, off);
                hi += __shfl_xor_sync(0xffffffffu, hi, off);
            }
            if (lane == 0 && row < n_nodes)
                ((unsigned long long*)(g_xw1 + (size_t)row * HID))[j] = pack2(lo, hi);
        }
    }
}

// ---------------------------------------------------------------------------
// Gather SpMM1: warp per row; 4 lanes per edge, each lane loads a float4 of
// the 16-wide x row => 8 independent edges in flight per warp.
__global__ __launch_bounds__(256) void spmm1_gather_kernel(int n_nodes)
{
    const int warp_id = (blockIdx.x * blockDim.x + threadIdx.x) >> 5;
    if (warp_id >= n_nodes) return;
    const int lane = threadIdx.x & 31;
    const int g  = lane >> 2;        // edge slot 0..7
    const int j4 = lane & 3;         // which float4 of 16

    const int start = g_rowptr[warp_id];
    const int end   = g_rowptr[warp_id + 1];

    float4 acc = make_float4(0.f, 0.f, 0.f, 0.f);
    for (int e = start + g; e < end; e += 8) {
        const int2 ev = __ldg(&g_csr[e]);
        const float v = __int_as_float(ev.y);
        const float4 x = __ldg((const float4*)(g_xw1 + (size_t)ev.x * HID) + j4);
        acc.x += v * x.x; acc.y += v * x.y; acc.z += v * x.z; acc.w += v * x.w;
    }
    #pragma unroll
    for (int off = 16; off >= 4; off >>= 1) {
        acc.x += __shfl_xor_sync(0xffffffffu, acc.x, off);
        acc.y += __shfl_xor_sync(0xffffffffu, acc.y, off);
        acc.z += __shfl_xor_sync(0xffffffffu, acc.z, off);
        acc.w += __shfl_xor_sync(0xffffffffu, acc.w, off);
    }
    if (g == 0)
        ((float4*)(g_h + (size_t)warp_id * HID))[j4] = acc;   // 64B coalesced
}

// ---------------------------------------------------------------------------
// GEMM2 (bias1 + ReLU fused): g_g[i, 0:7] = relu(g_h[i]+b1) @ W2, pad [7]=0
__global__ __launch_bounds__(256) void gemm2_kernel(
    const float* __restrict__ b1,
    const float* __restrict__ W2,
    int n_nodes)
{
    __shared__ float sW2[HID * OUTD];
    __shared__ float sb1[HID];
    if (threadIdx.x < HID * OUTD) sW2[threadIdx.x] = W2[threadIdx.x];
    if (threadIdx.x < HID)        sb1[threadIdx.x] = b1[threadIdx.x];
    __syncthreads();

    int i = blockIdx.x * blockDim.x + threadIdx.x;
    if (i >= n_nodes) return;

    float h[HID];
    const float4* hp = (const float4*)(g_h + (size_t)i * HID);
    #pragma unroll
    for (int q = 0; q < 4; q++) {
        float4 a = hp[q];
        h[4 * q + 0] = a.x; h[4 * q + 1] = a.y;
        h[4 * q + 2] = a.z; h[4 * q + 3] = a.w;
    }

    float o[OUTD];
    #pragma unroll
    for (int j = 0; j < OUTD; j++) o[j] = 0.0f;
    #pragma unroll
    for (int k = 0; k < HID; k++) {
        const float hv = fmaxf(h[k] + sb1[k], 0.0f);
        #pragma unroll
        for (int j = 0; j < OUTD; j++) o[j] += hv * sW2[k * OUTD + j];
    }

    float4* gp = (float4*)(g_g + (size_t)i * 8);
    gp[0] = make_float4(o[0], o[1], o[2], o[3]);
    gp[1] = make_float4(o[4], o[5], o[6], 0.0f);
}

// ---------------------------------------------------------------------------
// Gather SpMM2: warp per row; 2 lanes per edge (float4 each of the 8-wide g
// row) => 16 independent edges in flight. Writes final out with b2 fused.
__global__ __launch_bounds__(256) void spmm2_gather_kernel(
    float* __restrict__ out, const float* __restrict__ b2, int n_nodes)
{
    const int warp_id = (blockIdx.x * blockDim.x + threadIdx.x) >> 5;
    if (warp_id >= n_nodes) return;
    const int lane = threadIdx.x & 31;
    const int g  = lane >> 1;        // edge slot 0..15
    const int j4 = lane & 1;         // which float4 of 8

    const int start = g_rowptr[warp_id];
    const int end   = g_rowptr[warp_id + 1];

    float4 acc = make_float4(0.f, 0.f, 0.f, 0.f);
    for (int e = start + g; e < end; e += 16) {
        const int2 ev = __ldg(&g_csr[e]);
        const float v = __int_as_float(ev.y);
        const float4 x = __ldg((const float4*)(g_g + (size_t)ev.x * 8) + j4);
        acc.x += v * x.x; acc.y += v * x.y; acc.z += v * x.z; acc.w += v * x.w;
    }
    #pragma unroll
    for (int off = 16; off >= 2; off >>= 1) {
        acc.x += __shfl_xor_sync(0xffffffffu, acc.x, off);
        acc.y += __shfl_xor_sync(0xffffffffu, acc.y, off);
        acc.z += __shfl_xor_sync(0xffffffffu, acc.z, off);
        acc.w += __shfl_xor_sync(0xffffffffu, acc.w, off);
    }
    // lane 0 holds o[0..3], lane 1 holds o[4..6] (+pad)
    float* o = out + (size_t)warp_id * OUTD;
    if (lane == 0) {
        o[0] = acc.x + __ldg(b2 + 0);
        o[1] = acc.y + __ldg(b2 + 1);
        o[2] = acc.z + __ldg(b2 + 2);
        o[3] = acc.w + __ldg(b2 + 3);
    } else if (lane == 1) {
        o[4] = acc.x + __ldg(b2 + 4);
        o[5] = acc.y + __ldg(b2 + 5);
        o[6] = acc.z + __ldg(b2 + 6);
    }
}

// ---------------------------------------------------------------------------
extern "C" void kernel_launch(void* const* d_in, const int* in_sizes, int n_in,
                              void* d_out, int out_size)
{
    const void*  adj     = d_in[0];
    const float* vals    = (const float*)d_in[1];
    const float* feature = (const float*)d_in[2];
    const float* W1      = (const float*)d_in[3];
    const float* b1      = (const float*)d_in[4];
    const float* W2      = (const float*)d_in[5];
    const float* b2      = (const float*)d_in[6];
    float*       out     = (float*)d_out;

    const int n_edges = in_sizes[1];
    const int n_nodes = in_sizes[2] / IN_DIM;
    const int nb      = (n_nodes + 1023) / 1024;
    const int smem1   = IN_DIM * W1PAD * (int)sizeof(float);  // ~114.6 KB

    static bool attr_set = false;
    if (!attr_set) {
        cudaFuncSetAttribute(gemm1_kernel,
                             cudaFuncAttributeMaxDynamicSharedMemorySize, smem1);
        attr_set = true;
    }

    detect_idx_kernel<<<1, 1024>>>((const unsigned int*)adj, n_edges);
    zero_counts_kernel<<<nb, 1024>>>(n_nodes);

    gemm1_kernel<<<(n_nodes + 63) / 64, 512, smem1>>>(feature, W1, n_nodes);

    histogram_kernel<<<(n_edges + 255) / 256, 256>>>(adj, n_edges);
    scan1_kernel<<<nb, 1024>>>(n_nodes);
    scan2_kernel<<<1, 256>>>(nb);
    scan3_kernel<<<nb, 1024>>>(n_nodes);
    scatter_kernel<<<(n_edges + 255) / 256, 256>>>(adj, vals, n_edges);

    spmm1_gather_kernel<<<(n_nodes * 32 + 255) / 256, 256>>>(n_nodes);
    gemm2_kernel<<<(n_nodes + 255) / 256, 256>>>(b1, W2, n_nodes);
    spmm2_gather_kernel<<<(n_nodes * 32 + 255) / 256, 256>>>(out, b2, n_nodes);
}

// round 6
// speedup vs baseline: 4.2035x; 1.0133x over previous
#include <cuda_runtime.h>
#include <cstdint>

#define IN_DIM 1433
#define HID 16
#define OUTD 7
#define MAXN 200000
#define MAXE 6400000
#define MAXNB 256
#define W1PAD 20           // 80B row stride -> conflict-free LDS.128

// Scratch (__device__ globals; allocations are forbidden)
__device__ float g_xw1[(size_t)MAXN * HID];     // X @ W1                (12.8 MB)
__device__ float g_h[(size_t)MAXN * HID];       // A @ XW1               (12.8 MB)
__device__ float g_g[(size_t)MAXN * 8];         // relu(H+b1)@W2 pad8    ( 6.4 MB)
__device__ int2  g_csr[(size_t)MAXE];           // (col, val-bits)       (51.2 MB)
__device__ int   g_rowcnt[MAXN];
__device__ int   g_rowfill[MAXN];
__device__ int   g_rowptr[MAXN + 1];
__device__ int   g_blocksum[MAXNB];
__device__ int   g_blockoff[MAXNB];
__device__ int   g_idx64;

// ---------------------------------------------------------------------------
__device__ __forceinline__ unsigned long long pack2(float lo, float hi) {
    unsigned long long r;
    asm("mov.b64 %0, {%1, %2};" : "=l"(r) : "f"(lo), "f"(hi));
    return r;
}
__device__ __forceinline__ void unpack2(unsigned long long v, float& lo, float& hi) {
    asm("mov.b64 {%0, %1}, %2;" : "=f"(lo), "=f"(hi) : "l"(v));
}
__device__ __forceinline__ void ffma2(unsigned long long& d,
                                      unsigned long long a, unsigned long long b) {
    asm("fma.rn.f32x2 %0, %1, %2, %0;" : "+l"(d) : "l"(a), "l"(b));
}

// ---------------------------------------------------------------------------
__global__ void detect_idx_kernel(const unsigned int* __restrict__ adj_words, int n_edges)
{
    int i = threadIdx.x;
    int samples = n_edges < 1024 ? n_edges : 1024;
    int ok = 1;
    if (i < samples) ok = (adj_words[2 * i + 1] == 0u) ? 1 : 0;
    int all = __syncthreads_and(ok);
    if (i == 0) g_idx64 = all;
}

__device__ __forceinline__ int load_row(const void* adj, int e, int is64) {
    return is64 ? (int)__ldg((const long long*)adj + e)
                : __ldg((const int*)adj + e);
}
__device__ __forceinline__ int load_col(const void* adj, int e, int n_edges, int is64) {
    return is64 ? (int)__ldg((const long long*)adj + (size_t)n_edges + e)
                : __ldg((const int*)adj + (size_t)n_edges + e);
}

// ---------------------------------------------------------------------------
__global__ void zero_counts_kernel(int n)
{
    int i = blockIdx.x * blockDim.x + threadIdx.x;
    if (i < n) { g_rowcnt[i] = 0; g_rowfill[i] = 0; }
}

// ---------------------------------------------------------------------------
// CSR build
__global__ __launch_bounds__(256) void histogram_kernel(
    const void* __restrict__ adj, int n_edges)
{
    int e = blockIdx.x * blockDim.x + threadIdx.x;
    if (e >= n_edges) return;
    int r = load_row(adj, e, g_idx64);
    atomicAdd(&g_rowcnt[r], 1);
}

__device__ __forceinline__ int block_excl_scan(int v, int* warp_sums, int nwarps)
{
    const int lane = threadIdx.x & 31, w = threadIdx.x >> 5;
    int x = v;
    #pragma unroll
    for (int off = 1; off < 32; off <<= 1) {
        int y = __shfl_up_sync(0xffffffffu, x, off);
        if (lane >= off) x += y;
    }
    if (lane == 31) warp_sums[w] = x;
    __syncthreads();
    if (w == 0) {
        int s = (lane < nwarps) ? warp_sums[lane] : 0;
        #pragma unroll
        for (int off = 1; off < 32; off <<= 1) {
            int y = __shfl_up_sync(0xffffffffu, s, off);
            if (lane >= off) s += y;
        }
        if (lane < nwarps) warp_sums[lane] = s;
    }
    __syncthreads();
    int base = (w > 0) ? warp_sums[w - 1] : 0;
    return base + x - v;
}

__global__ __launch_bounds__(1024) void scan1_kernel(int n)
{
    __shared__ int ws[32];
    int i = blockIdx.x * 1024 + threadIdx.x;
    int v = (i < n) ? g_rowcnt[i] : 0;
    int ex = block_excl_scan(v, ws, 32);
    if (threadIdx.x == 1023) g_blocksum[blockIdx.x] = ex + v;
}

__global__ __launch_bounds__(256) void scan2_kernel(int nb)
{
    __shared__ int ws[32];
    int i = threadIdx.x;
    int v = (i < nb) ? g_blocksum[i] : 0;
    int ex = block_excl_scan(v, ws, 8);
    if (i < nb) g_blockoff[i] = ex;
}

__global__ __launch_bounds__(1024) void scan3_kernel(int n)
{
    __shared__ int ws[32];
    int i = blockIdx.x * 1024 + threadIdx.x;
    int v = (i < n) ? g_rowcnt[i] : 0;
    int ex = block_excl_scan(v, ws, 32);
    int base = g_blockoff[blockIdx.x];
    if (i < n)      g_rowptr[i] = base + ex;
    if (i == n - 1) g_rowptr[n] = base + ex + v;
}

__global__ __launch_bounds__(256) void scatter_kernel(
    const void* __restrict__ adj, const float* __restrict__ vals, int n_edges)
{
    int e = blockIdx.x * blockDim.x + threadIdx.x;
    if (e >= n_edges) return;
    const int is64 = g_idx64;
    int r = load_row(adj, e, is64);
    int c = load_col(adj, e, n_edges, is64);
    float v = __ldg(vals + e);
    int pos = g_rowptr[r] + atomicAdd(&g_rowfill[r], 1);
    g_csr[pos] = make_int2(c, __float_as_int(v));
}

// ---------------------------------------------------------------------------
// GEMM1: XW1 = feature @ W1.  512 thr = 16 warps x 4 rows; lanes split K.
// k-loop unrolled x4: 16 DRAM loads batched per warp-iter.
// W1 rows loaded from smem as ulonglong2 -> f32x2 operands with zero MOVs.
__global__ __launch_bounds__(512, 1) void gemm1_kernel(
    const float* __restrict__ feature,
    const float* __restrict__ W1,
    int n_nodes)
{
    extern __shared__ float sW1[];   // IN_DIM * W1PAD
    for (int i = threadIdx.x; i < IN_DIM * HID; i += 512) {
        int k = i >> 4, j = i & 15;
        sW1[k * W1PAD + j] = W1[i];
    }
    __syncthreads();

    const int warp = threadIdx.x >> 5;
    const int lane = threadIdx.x & 31;
    const int row0 = blockIdx.x * 64 + warp * 4;
    const bool rowsok = (row0 + 3 < n_nodes);

    unsigned long long acc[4][8];
    #pragma unroll
    for (int r = 0; r < 4; r++)
        #pragma unroll
        for (int j = 0; j < 8; j++) acc[r][j] = 0ull;

    for (int kb = 0; kb < IN_DIM; kb += 128) {
        int  kk[4];
        bool kv[4];
        #pragma unroll
        for (int s = 0; s < 4; s++) {
            int k = kb + s * 32 + lane;
            kv[s] = (k < IN_DIM);
            kk[s] = kv[s] ? k : 0;
        }

        // Batch all 16 global loads first (16 LDGs in flight per warp).
        float f[4][4];
        if (rowsok && kb + 127 < IN_DIM) {
            #pragma unroll
            for (int r = 0; r < 4; r++) {
                const float* fr = feature + (size_t)(row0 + r) * IN_DIM + lane + kb;
                #pragma unroll
                for (int s = 0; s < 4; s++) f[r][s] = __ldg(fr + s * 32);
            }
        } else {
            #pragma unroll
            for (int r = 0; r < 4; r++) {
                const bool rv = (row0 + r < n_nodes);
                const float* fr = feature + (size_t)(row0 + r) * IN_DIM;
                #pragma unroll
                for (int s = 0; s < 4; s++)
                    f[r][s] = (rv && kv[s]) ? __ldg(fr + kb + s * 32 + lane) : 0.0f;
            }
        }

        #pragma unroll
        for (int s = 0; s < 4; s++) {
            // 4x LDS.128 as u64 pairs: operands land directly in paired regs.
            const ulonglong2* wp = (const ulonglong2*)(sW1 + kk[s] * W1PAD);
            const ulonglong2 q0 = wp[0], q1 = wp[1], q2 = wp[2], q3 = wp[3];
            #pragma unroll
            for (int r = 0; r < 4; r++) {
                const unsigned long long fr2 = pack2(f[r][s], f[r][s]);
                ffma2(acc[r][0], fr2, q0.x);
                ffma2(acc[r][1], fr2, q0.y);
                ffma2(acc[r][2], fr2, q1.x);
                ffma2(acc[r][3], fr2, q1.y);
                ffma2(acc[r][4], fr2, q2.x);
                ffma2(acc[r][5], fr2, q2.y);
                ffma2(acc[r][6], fr2, q3.x);
                ffma2(acc[r][7], fr2, q3.y);
            }
        }
    }

    #pragma unroll
    for (int r = 0; r < 4; r++) {
        const int row = row0 + r;
        #pragma unroll
        for (int j = 0; j < 8; j++) {
            float lo, hi;
            unpack2(acc[r][j], lo, hi);
            #pragma unroll
            for (int off = 16; off; off >>= 1) {
                lo += __shfl_xor_sync(0xffffffffu, lo, off);
                hi += __shfl_xor_sync(0xffffffffu, hi, off);
            }
            if (lane == 0 && row < n_nodes)
                ((unsigned long long*)(g_xw1 + (size_t)row * HID))[j] = pack2(lo, hi);
        }
    }
}

// ---------------------------------------------------------------------------
// Gather SpMM1: warp per row; 4 lanes per edge (float4 each of 16-wide row)
// => 8 independent edges in flight per warp. No atomics.
__global__ __launch_bounds__(256) void spmm1_gather_kernel(int n_nodes)
{
    const int warp_id = (blockIdx.x * blockDim.x + threadIdx.x) >> 5;
    if (warp_id >= n_nodes) return;
    const int lane = threadIdx.x & 31;
    const int g  = lane >> 2;
    const int j4 = lane & 3;

    const int start = g_rowptr[warp_id];
    const int end   = g_rowptr[warp_id + 1];

    float4 acc = make_float4(0.f, 0.f, 0.f, 0.f);
    for (int e = start + g; e < end; e += 8) {
        const int2 ev = __ldg(&g_csr[e]);
        const float v = __int_as_float(ev.y);
        const float4 x = __ldg((const float4*)(g_xw1 + (size_t)ev.x * HID) + j4);
        acc.x += v * x.x; acc.y += v * x.y; acc.z += v * x.z; acc.w += v * x.w;
    }
    #pragma unroll
    for (int off = 16; off >= 4; off >>= 1) {
        acc.x += __shfl_xor_sync(0xffffffffu, acc.x, off);
        acc.y += __shfl_xor_sync(0xffffffffu, acc.y, off);
        acc.z += __shfl_xor_sync(0xffffffffu, acc.z, off);
        acc.w += __shfl_xor_sync(0xffffffffu, acc.w, off);
    }
    if (g == 0)
        ((float4*)(g_h + (size_t)warp_id * HID))[j4] = acc;
}

// ---------------------------------------------------------------------------
// GEMM2 (bias1 + ReLU fused): g_g[i, 0:7] = relu(g_h[i]+b1) @ W2, pad [7]=0
__global__ __launch_bounds__(256) void gemm2_kernel(
    const float* __restrict__ b1,
    const float* __restrict__ W2,
    int n_nodes)
{
    __shared__ float sW2[HID * OUTD];
    __shared__ float sb1[HID];
    if (threadIdx.x < HID * OUTD) sW2[threadIdx.x] = W2[threadIdx.x];
    if (threadIdx.x < HID)        sb1[threadIdx.x] = b1[threadIdx.x];
    __syncthreads();

    int i = blockIdx.x * blockDim.x + threadIdx.x;
    if (i >= n_nodes) return;

    float h[HID];
    const float4* hp = (const float4*)(g_h + (size_t)i * HID);
    #pragma unroll
    for (int q = 0; q < 4; q++) {
        float4 a = hp[q];
        h[4 * q + 0] = a.x; h[4 * q + 1] = a.y;
        h[4 * q + 2] = a.z; h[4 * q + 3] = a.w;
    }

    float o[OUTD];
    #pragma unroll
    for (int j = 0; j < OUTD; j++) o[j] = 0.0f;
    #pragma unroll
    for (int k = 0; k < HID; k++) {
        const float hv = fmaxf(h[k] + sb1[k], 0.0f);
        #pragma unroll
        for (int j = 0; j < OUTD; j++) o[j] += hv * sW2[k * OUTD + j];
    }

    float4* gp = (float4*)(g_g + (size_t)i * 8);
    gp[0] = make_float4(o[0], o[1], o[2], o[3]);
    gp[1] = make_float4(o[4], o[5], o[6], 0.0f);
}

// ---------------------------------------------------------------------------
// Gather SpMM2: warp per row; 2 lanes per edge => 16 edges in flight.
__global__ __launch_bounds__(256) void spmm2_gather_kernel(
    float* __restrict__ out, const float* __restrict__ b2, int n_nodes)
{
    const int warp_id = (blockIdx.x * blockDim.x + threadIdx.x) >> 5;
    if (warp_id >= n_nodes) return;
    const int lane = threadIdx.x & 31;
    const int g  = lane >> 1;
    const int j4 = lane & 1;

    const int start = g_rowptr[warp_id];
    const int end   = g_rowptr[warp_id + 1];

    float4 acc = make_float4(0.f, 0.f, 0.f, 0.f);
    for (int e = start + g; e < end; e += 16) {
        const int2 ev = __ldg(&g_csr[e]);
        const float v = __int_as_float(ev.y);
        const float4 x = __ldg((const float4*)(g_g + (size_t)ev.x * 8) + j4);
        acc.x += v * x.x; acc.y += v * x.y; acc.z += v * x.z; acc.w += v * x.w;
    }
    #pragma unroll
    for (int off = 16; off >= 2; off >>= 1) {
        acc.x += __shfl_xor_sync(0xffffffffu, acc.x, off);
        acc.y += __shfl_xor_sync(0xffffffffu, acc.y, off);
        acc.z += __shfl_xor_sync(0xffffffffu, acc.z, off);
        acc.w += __shfl_xor_sync(0xffffffffu, acc.w, off);
    }
    float* o = out + (size_t)warp_id * OUTD;
    if (lane == 0) {
        o[0] = acc.x + __ldg(b2 + 0);
        o[1] = acc.y + __ldg(b2 + 1);
        o[2] = acc.z + __ldg(b2 + 2);
        o[3] = acc.w + __ldg(b2 + 3);
    } else if (lane == 1) {
        o[4] = acc.x + __ldg(b2 + 4);
        o[5] = acc.y + __ldg(b2 + 5);
        o[6] = acc.z + __ldg(b2 + 6);
    }
}

// ---------------------------------------------------------------------------
extern "C" void kernel_launch(void* const* d_in, const int* in_sizes, int n_in,
                              void* d_out, int out_size)
{
    const void*  adj     = d_in[0];
    const float* vals    = (const float*)d_in[1];
    const float* feature = (const float*)d_in[2];
    const float* W1      = (const float*)d_in[3];
    const float* b1      = (const float*)d_in[4];
    const float* W2      = (const float*)d_in[5];
    const float* b2      = (const float*)d_in[6];
    float*       out     = (float*)d_out;

    const int n_edges = in_sizes[1];
    const int n_nodes = in_sizes[2] / IN_DIM;
    const int nb      = (n_nodes + 1023) / 1024;
    const int smem1   = IN_DIM * W1PAD * (int)sizeof(float);  // ~114.6 KB

    static cudaStream_t s2 = nullptr;
    static cudaEvent_t ev_fork = nullptr, ev_join = nullptr;
    if (!s2) {
        cudaFuncSetAttribute(gemm1_kernel,
                             cudaFuncAttributeMaxDynamicSharedMemorySize, smem1);
        cudaStreamCreateWithFlags(&s2, cudaStreamNonBlocking);
        cudaEventCreateWithFlags(&ev_fork, cudaEventDisableTiming);
        cudaEventCreateWithFlags(&ev_join, cudaEventDisableTiming);
    }

    // Fork: CSR build chain on side stream (atomic/L2-bound, no smem) runs
    // concurrently with gemm1 (DRAM/FMA-bound, only 16 warps/SM).
    cudaEventRecord(ev_fork, 0);
    cudaStreamWaitEvent(s2, ev_fork, 0);

    detect_idx_kernel<<<1, 1024, 0, s2>>>((const unsigned int*)adj, n_edges);
    zero_counts_kernel<<<nb, 1024, 0, s2>>>(n_nodes);
    histogram_kernel<<<(n_edges + 255) / 256, 256, 0, s2>>>(adj, n_edges);
    scan1_kernel<<<nb, 1024, 0, s2>>>(n_nodes);
    scan2_kernel<<<1, 256, 0, s2>>>(nb);
    scan3_kernel<<<nb, 1024, 0, s2>>>(n_nodes);
    scatter_kernel<<<(n_edges + 255) / 256, 256, 0, s2>>>(adj, vals, n_edges);
    cudaEventRecord(ev_join, s2);

    // Main stream: dense layer 1 in parallel with the CSR build.
    gemm1_kernel<<<(n_nodes + 63) / 64, 512, smem1>>>(feature, W1, n_nodes);

    // Join, then the dependent chain.
    cudaStreamWaitEvent(0, ev_join, 0);
    spmm1_gather_kernel<<<(n_nodes * 32 + 255) / 256, 256>>>(n_nodes);
    gemm2_kernel<<<(n_nodes + 255) / 256, 256>>>(b1, W2, n_nodes);
    spmm2_gather_kernel<<<(n_nodes * 32 + 255) / 256, 256>>>(out, b2, n_nodes);
}

// round 7
// speedup vs baseline: 4.6021x; 1.0948x over previous
#include <cuda_runtime.h>
#include <cstdint>

#define IN_DIM 1433
#define HID 16
#define OUTD 7
#define MAXN 200000
#define MAXE 6400000
#define MAXNB 256
#define W1PAD 20           // 80B row stride -> conflict-free LDS.128

// Scratch (__device__ globals; allocations are forbidden)
__device__ float g_xw1[(size_t)MAXN * HID];
__device__ float g_h[(size_t)MAXN * HID];
__device__ float g_g[(size_t)MAXN * 8];
__device__ int2  g_csr[(size_t)MAXE];
__device__ int   g_rowcnt[MAXN];
__device__ int   g_rowfill[MAXN];
__device__ int   g_rowptr[MAXN + 1];
__device__ int   g_blocksum[MAXNB];
__device__ int   g_blockoff[MAXNB];
__device__ int   g_idx64;

// ---------------------------------------------------------------------------
__device__ __forceinline__ unsigned long long pack2(float lo, float hi) {
    unsigned long long r;
    asm("mov.b64 %0, {%1, %2};" : "=l"(r) : "f"(lo), "f"(hi));
    return r;
}
__device__ __forceinline__ void unpack2(unsigned long long v, float& lo, float& hi) {
    asm("mov.b64 {%0, %1}, %2;" : "=f"(lo), "=f"(hi) : "l"(v));
}
__device__ __forceinline__ void ffma2(unsigned long long& d,
                                      unsigned long long a, unsigned long long b) {
    asm("fma.rn.f32x2 %0, %1, %2, %0;" : "+l"(d) : "l"(a), "l"(b));
}

// ---------------------------------------------------------------------------
__global__ void detect_idx_kernel(const unsigned int* __restrict__ adj_words, int n_edges)
{
    int i = threadIdx.x;
    int samples = n_edges < 1024 ? n_edges : 1024;
    int ok = 1;
    if (i < samples) ok = (adj_words[2 * i + 1] == 0u) ? 1 : 0;
    int all = __syncthreads_and(ok);
    if (i == 0) g_idx64 = all;
}

__device__ __forceinline__ int load_row(const void* adj, int e, int is64) {
    return is64 ? (int)__ldg((const long long*)adj + e)
                : __ldg((const int*)adj + e);
}
__device__ __forceinline__ int load_col(const void* adj, int e, int n_edges, int is64) {
    return is64 ? (int)__ldg((const long long*)adj + (size_t)n_edges + e)
                : __ldg((const int*)adj + (size_t)n_edges + e);
}

// ---------------------------------------------------------------------------
__global__ void zero_counts_kernel(int n)
{
    int i = blockIdx.x * blockDim.x + threadIdx.x;
    if (i < n) { g_rowcnt[i] = 0; g_rowfill[i] = 0; }
}

// ---------------------------------------------------------------------------
__global__ __launch_bounds__(256) void histogram_kernel(
    const void* __restrict__ adj, int n_edges)
{
    int e = blockIdx.x * blockDim.x + threadIdx.x;
    if (e >= n_edges) return;
    int r = load_row(adj, e, g_idx64);
    atomicAdd(&g_rowcnt[r], 1);
}

__device__ __forceinline__ int block_excl_scan(int v, int* warp_sums, int nwarps)
{
    const int lane = threadIdx.x & 31, w = threadIdx.x >> 5;
    int x = v;
    #pragma unroll
    for (int off = 1; off < 32; off <<= 1) {
        int y = __shfl_up_sync(0xffffffffu, x, off);
        if (lane >= off) x += y;
    }
    if (lane == 31) warp_sums[w] = x;
    __syncthreads();
    if (w == 0) {
        int s = (lane < nwarps) ? warp_sums[lane] : 0;
        #pragma unroll
        for (int off = 1; off < 32; off <<= 1) {
            int y = __shfl_up_sync(0xffffffffu, s, off);
            if (lane >= off) s += y;
        }
        if (lane < nwarps) warp_sums[lane] = s;
    }
    __syncthreads();
    int base = (w > 0) ? warp_sums[w - 1] : 0;
    return base + x - v;
}

__global__ __launch_bounds__(1024) void scan1_kernel(int n)
{
    __shared__ int ws[32];
    int i = blockIdx.x * 1024 + threadIdx.x;
    int v = (i < n) ? g_rowcnt[i] : 0;
    int ex = block_excl_scan(v, ws, 32);
    if (threadIdx.x == 1023) g_blocksum[blockIdx.x] = ex + v;
}

__global__ __launch_bounds__(256) void scan2_kernel(int nb)
{
    __shared__ int ws[32];
    int i = threadIdx.x;
    int v = (i < nb) ? g_blocksum[i] : 0;
    int ex = block_excl_scan(v, ws, 8);
    if (i < nb) g_blockoff[i] = ex;
}

__global__ __launch_bounds__(1024) void scan3_kernel(int n)
{
    __shared__ int ws[32];
    int i = blockIdx.x * 1024 + threadIdx.x;
    int v = (i < n) ? g_rowcnt[i] : 0;
    int ex = block_excl_scan(v, ws, 32);
    int base = g_blockoff[blockIdx.x];
    if (i < n)      g_rowptr[i] = base + ex;
    if (i == n - 1) g_rowptr[n] = base + ex + v;
}

__global__ __launch_bounds__(256) void scatter_kernel(
    const void* __restrict__ adj, const float* __restrict__ vals, int n_edges)
{
    int e = blockIdx.x * blockDim.x + threadIdx.x;
    if (e >= n_edges) return;
    const int is64 = g_idx64;
    int r = load_row(adj, e, is64);
    int c = load_col(adj, e, n_edges, is64);
    float v = __ldg(vals + e);
    int pos = g_rowptr[r] + atomicAdd(&g_rowfill[r], 1);
    g_csr[pos] = make_int2(c, __float_as_int(v));
}

// ---------------------------------------------------------------------------
// GEMM1 (persistent): XW1 = feature @ W1.
// Grid = #SMs; W1 staged in smem ONCE; warps stride independently over
// row-quads (no __syncthreads in the loop — smem is read-only).
// Per k-iter: batch 16 LDGs with 1-deep prefetch of the next iter's 16.
__global__ __launch_bounds__(512, 1) void gemm1_kernel(
    const float* __restrict__ feature,
    const float* __restrict__ W1,
    int n_nodes, int nquads)
{
    extern __shared__ float sW1[];   // IN_DIM * W1PAD
    for (int i = threadIdx.x; i < IN_DIM * HID; i += 512) {
        int k = i >> 4, j = i & 15;
        sW1[k * W1PAD + j] = W1[i];
    }
    __syncthreads();

    const int warp   = threadIdx.x >> 5;
    const int lane   = threadIdx.x & 31;
    const int gwarp  = blockIdx.x * 16 + warp;
    const int nwarps = gridDim.x * 16;

    const int NKB    = IN_DIM / 128;          // 11 full 128-wide k-blocks
    const int KMAIN  = NKB * 128;             // 1408

    for (int q = gwarp; q < nquads; q += nwarps) {
        const int row0 = q * 4;
        const bool rowsok = (row0 + 3 < n_nodes);

        unsigned long long acc[4][8];
        #pragma unroll
        for (int r = 0; r < 4; r++)
            #pragma unroll
            for (int j = 0; j < 8; j++) acc[r][j] = 0ull;

        float f[4][4], fn[4][4];

        // --- preload kb = 0 (always full: IN_DIM > 128) ---
        if (rowsok) {
            #pragma unroll
            for (int r = 0; r < 4; r++) {
                const float* fr = feature + (size_t)(row0 + r) * IN_DIM + lane;
                #pragma unroll
                for (int s = 0; s < 4; s++) f[r][s] = __ldg(fr + s * 32);
            }
        } else {
            #pragma unroll
            for (int r = 0; r < 4; r++) {
                const bool rv = (row0 + r < n_nodes);
                const float* fr = feature + (size_t)(row0 + r) * IN_DIM + lane;
                #pragma unroll
                for (int s = 0; s < 4; s++) f[r][s] = rv ? __ldg(fr + s * 32) : 0.0f;
            }
        }

        for (int kb = 0; kb < KMAIN; kb += 128) {
            // --- prefetch next k-block (full blocks only) ---
            const int kn = kb + 128;
            if (kn < KMAIN) {
                if (rowsok) {
                    #pragma unroll
                    for (int r = 0; r < 4; r++) {
                        const float* fr = feature + (size_t)(row0 + r) * IN_DIM + lane + kn;
                        #pragma unroll
                        for (int s = 0; s < 4; s++) fn[r][s] = __ldg(fr + s * 32);
                    }
                } else {
                    #pragma unroll
                    for (int r = 0; r < 4; r++) {
                        const bool rv = (row0 + r < n_nodes);
                        const float* fr = feature + (size_t)(row0 + r) * IN_DIM + lane + kn;
                        #pragma unroll
                        for (int s = 0; s < 4; s++) fn[r][s] = rv ? __ldg(fr + s * 32) : 0.0f;
                    }
                }
            }

            // --- compute current k-block ---
            #pragma unroll
            for (int s = 0; s < 4; s++) {
                const int k = kb + s * 32 + lane;
                const ulonglong2* wp = (const ulonglong2*)(sW1 + k * W1PAD);
                const ulonglong2 q0 = wp[0], q1 = wp[1];
                #pragma unroll
                for (int r = 0; r < 4; r++) {
                    const unsigned long long fr2 = pack2(f[r][s], f[r][s]);
                    ffma2(acc[r][0], fr2, q0.x);
                    ffma2(acc[r][1], fr2, q0.y);
                    ffma2(acc[r][2], fr2, q1.x);
                    ffma2(acc[r][3], fr2, q1.y);
                }
                const ulonglong2 q2 = wp[2], q3 = wp[3];
                #pragma unroll
                for (int r = 0; r < 4; r++) {
                    const unsigned long long fr2 = pack2(f[r][s], f[r][s]);
                    ffma2(acc[r][4], fr2, q2.x);
                    ffma2(acc[r][5], fr2, q2.y);
                    ffma2(acc[r][6], fr2, q3.x);
                    ffma2(acc[r][7], fr2, q3.y);
                }
            }

            if (kn < KMAIN) {
                #pragma unroll
                for (int r = 0; r < 4; r++)
                    #pragma unroll
                    for (int s = 0; s < 4; s++) f[r][s] = fn[r][s];
            }
        }

        // --- tail: k = 1408 .. 1432 (25 values, one predicated slice) ---
        {
            const int k = KMAIN + lane;
            const bool kv = (k < IN_DIM);
            const int ke = kv ? k : 0;
            float ft[4];
            #pragma unroll
            for (int r = 0; r < 4; r++) {
                const bool rv = (row0 + r < n_nodes);
                ft[r] = (kv && rv) ? __ldg(feature + (size_t)(row0 + r) * IN_DIM + k)
                                   : 0.0f;
            }
            const ulonglong2* wp = (const ulonglong2*)(sW1 + ke * W1PAD);
            const ulonglong2 q0 = wp[0], q1 = wp[1], q2 = wp[2], q3 = wp[3];
            #pragma unroll
            for (int r = 0; r < 4; r++) {
                const unsigned long long fr2 = pack2(ft[r], ft[r]);
                ffma2(acc[r][0], fr2, q0.x);
                ffma2(acc[r][1], fr2, q0.y);
                ffma2(acc[r][2], fr2, q1.x);
                ffma2(acc[r][3], fr2, q1.y);
                ffma2(acc[r][4], fr2, q2.x);
                ffma2(acc[r][5], fr2, q2.y);
                ffma2(acc[r][6], fr2, q3.x);
                ffma2(acc[r][7], fr2, q3.y);
            }
        }

        // --- reduce + store ---
        #pragma unroll
        for (int r = 0; r < 4; r++) {
            const int row = row0 + r;
            #pragma unroll
            for (int j = 0; j < 8; j++) {
                float lo, hi;
                unpack2(acc[r][j], lo, hi);
                #pragma unroll
                for (int off = 16; off; off >>= 1) {
                    lo += __shfl_xor_sync(0xffffffffu, lo, off);
                    hi += __shfl_xor_sync(0xffffffffu, hi, off);
                }
                if (lane == 0 && row < n_nodes)
                    ((unsigned long long*)(g_xw1 + (size_t)row * HID))[j] = pack2(lo, hi);
            }
        }
    }
}

// ---------------------------------------------------------------------------
__global__ __launch_bounds__(256) void spmm1_gather_kernel(int n_nodes)
{
    const int warp_id = (blockIdx.x * blockDim.x + threadIdx.x) >> 5;
    if (warp_id >= n_nodes) return;
    const int lane = threadIdx.x & 31;
    const int g  = lane >> 2;
    const int j4 = lane & 3;

    const int start = g_rowptr[warp_id];
    const int end   = g_rowptr[warp_id + 1];

    float4 acc = make_float4(0.f, 0.f, 0.f, 0.f);
    for (int e = start + g; e < end; e += 8) {
        const int2 ev = __ldg(&g_csr[e]);
        const float v = __int_as_float(ev.y);
        const float4 x = __ldg((const float4*)(g_xw1 + (size_t)ev.x * HID) + j4);
        acc.x += v * x.x; acc.y += v * x.y; acc.z += v * x.z; acc.w += v * x.w;
    }
    #pragma unroll
    for (int off = 16; off >= 4; off >>= 1) {
        acc.x += __shfl_xor_sync(0xffffffffu, acc.x, off);
        acc.y += __shfl_xor_sync(0xffffffffu, acc.y, off);
        acc.z += __shfl_xor_sync(0xffffffffu, acc.z, off);
        acc.w += __shfl_xor_sync(0xffffffffu, acc.w, off);
    }
    if (g == 0)
        ((float4*)(g_h + (size_t)warp_id * HID))[j4] = acc;
}

// ---------------------------------------------------------------------------
__global__ __launch_bounds__(256) void gemm2_kernel(
    const float* __restrict__ b1,
    const float* __restrict__ W2,
    int n_nodes)
{
    __shared__ float sW2[HID * OUTD];
    __shared__ float sb1[HID];
    if (threadIdx.x < HID * OUTD) sW2[threadIdx.x] = W2[threadIdx.x];
    if (threadIdx.x < HID)        sb1[threadIdx.x] = b1[threadIdx.x];
    __syncthreads();

    int i = blockIdx.x * blockDim.x + threadIdx.x;
    if (i >= n_nodes) return;

    float h[HID];
    const float4* hp = (const float4*)(g_h + (size_t)i * HID);
    #pragma unroll
    for (int q = 0; q < 4; q++) {
        float4 a = hp[q];
        h[4 * q + 0] = a.x; h[4 * q + 1] = a.y;
        h[4 * q + 2] = a.z; h[4 * q + 3] = a.w;
    }

    float o[OUTD];
    #pragma unroll
    for (int j = 0; j < OUTD; j++) o[j] = 0.0f;
    #pragma unroll
    for (int k = 0; k < HID; k++) {
        const float hv = fmaxf(h[k] + sb1[k], 0.0f);
        #pragma unroll
        for (int j = 0; j < OUTD; j++) o[j] += hv * sW2[k * OUTD + j];
    }

    float4* gp = (float4*)(g_g + (size_t)i * 8);
    gp[0] = make_float4(o[0], o[1], o[2], o[3]);
    gp[1] = make_float4(o[4], o[5], o[6], 0.0f);
}

// ---------------------------------------------------------------------------
__global__ __launch_bounds__(256) void spmm2_gather_kernel(
    float* __restrict__ out, const float* __restrict__ b2, int n_nodes)
{
    const int warp_id = (blockIdx.x * blockDim.x + threadIdx.x) >> 5;
    if (warp_id >= n_nodes) return;
    const int lane = threadIdx.x & 31;
    const int g  = lane >> 1;
    const int j4 = lane & 1;

    const int start = g_rowptr[warp_id];
    const int end   = g_rowptr[warp_id + 1];

    float4 acc = make_float4(0.f, 0.f, 0.f, 0.f);
    for (int e = start + g; e < end; e += 16) {
        const int2 ev = __ldg(&g_csr[e]);
        const float v = __int_as_float(ev.y);
        const float4 x = __ldg((const float4*)(g_g + (size_t)ev.x * 8) + j4);
        acc.x += v * x.x; acc.y += v * x.y; acc.z += v * x.z; acc.w += v * x.w;
    }
    #pragma unroll
    for (int off = 16; off >= 2; off >>= 1) {
        acc.x += __shfl_xor_sync(0xffffffffu, acc.x, off);
        acc.y += __shfl_xor_sync(0xffffffffu, acc.y, off);
        acc.z += __shfl_xor_sync(0xffffffffu, acc.z, off);
        acc.w += __shfl_xor_sync(0xffffffffu, acc.w, off);
    }
    float* o = out + (size_t)warp_id * OUTD;
    if (lane == 0) {
        o[0] = acc.x + __ldg(b2 + 0);
        o[1] = acc.y + __ldg(b2 + 1);
        o[2] = acc.z + __ldg(b2 + 2);
        o[3] = acc.w + __ldg(b2 + 3);
    } else if (lane == 1) {
        o[4] = acc.x + __ldg(b2 + 4);
        o[5] = acc.y + __ldg(b2 + 5);
        o[6] = acc.z + __ldg(b2 + 6);
    }
}

// ---------------------------------------------------------------------------
extern "C" void kernel_launch(void* const* d_in, const int* in_sizes, int n_in,
                              void* d_out, int out_size)
{
    const void*  adj     = d_in[0];
    const float* vals    = (const float*)d_in[1];
    const float* feature = (const float*)d_in[2];
    const float* W1      = (const float*)d_in[3];
    const float* b1      = (const float*)d_in[4];
    const float* W2      = (const float*)d_in[5];
    const float* b2      = (const float*)d_in[6];
    float*       out     = (float*)d_out;

    const int n_edges = in_sizes[1];
    const int n_nodes = in_sizes[2] / IN_DIM;
    const int nquads  = (n_nodes + 3) / 4;
    const int nb      = (n_nodes + 1023) / 1024;
    const int smem1   = IN_DIM * W1PAD * (int)sizeof(float);  // ~114.6 KB

    static cudaStream_t s2 = nullptr;
    static cudaEvent_t ev_fork = nullptr, ev_join = nullptr;
    static int n_sms = 148;
    if (!s2) {
        cudaFuncSetAttribute(gemm1_kernel,
                             cudaFuncAttributeMaxDynamicSharedMemorySize, smem1);
        cudaStreamCreateWithFlags(&s2, cudaStreamNonBlocking);
        cudaEventCreateWithFlags(&ev_fork, cudaEventDisableTiming);
        cudaEventCreateWithFlags(&ev_join, cudaEventDisableTiming);
        int dev = 0;
        cudaGetDevice(&dev);
        cudaDeviceGetAttribute(&n_sms, cudaDevAttrMultiProcessorCount, dev);
    }

    // Fork: CSR build on side stream concurrently with persistent gemm1.
    cudaEventRecord(ev_fork, 0);
    cudaStreamWaitEvent(s2, ev_fork, 0);

    detect_idx_kernel<<<1, 1024, 0, s2>>>((const unsigned int*)adj, n_edges);
    zero_counts_kernel<<<nb, 1024, 0, s2>>>(n_nodes);
    histogram_kernel<<<(n_edges + 255) / 256, 256, 0, s2>>>(adj, n_edges);
    scan1_kernel<<<nb, 1024, 0, s2>>>(n_nodes);
    scan2_kernel<<<1, 256, 0, s2>>>(nb);
    scan3_kernel<<<nb, 1024, 0, s2>>>(n_nodes);
    scatter_kernel<<<(n_edges + 255) / 256, 256, 0, s2>>>(adj, vals, n_edges);
    cudaEventRecord(ev_join, s2);

    // Main stream: persistent dense layer 1.
    gemm1_kernel<<<n_sms, 512, smem1>>>(feature, W1, n_nodes, nquads);

    // Join, then dependent chain.
    cudaStreamWaitEvent(0, ev_join, 0);
    spmm1_gather_kernel<<<(n_nodes * 32 + 255) / 256, 256>>>(n_nodes);
    gemm2_kernel<<<(n_nodes + 255) / 256, 256>>>(b1, W2, n_nodes);
    spmm2_gather_kernel<<<(n_nodes * 32 + 255) / 256, 256>>>(out, b2, n_nodes);
}

// round 9
// speedup vs baseline: 4.7242x; 1.0265x over previous
#include <cuda_runtime.h>
#include <cstdint>

#define IN_DIM 1433
#define HID 16
#define OUTD 7
#define MAXN 200000
#define MAXE 6400000
#define MAXNB 256

// gemm1 mma.sync tiling
#define KSTEPS_FULL 89           // 89*16 = 1424 (all k in-bounds)
#define KP 1448                  // smem pitch (bf16 elems) -> 724 words, 724%32=20 (conflict-free)
#define KPW (KP / 2)             // 724 u32 words per n-row
#define SMEM_BHALF (16 * KP * 2) // 46336 B per split half
#define SMEM_B_BYTES (2 * SMEM_BHALF)

// Scratch (__device__ globals; allocations are forbidden)
__device__ float g_xw1[(size_t)MAXN * HID];
__device__ float g_h[(size_t)MAXN * HID];
__device__ float g_g[(size_t)MAXN * 8];
__device__ int2  g_csr[(size_t)MAXE];
__device__ int   g_rowcnt[MAXN];
__device__ int   g_rowfill[MAXN];
__device__ int   g_rowptr[MAXN + 1];
__device__ int   g_blocksum[MAXNB];
__device__ int   g_blockoff[MAXNB];
__device__ int   g_idx64;

// ---------------------------------------------------------------------------
// Split fp32 pair -> packed bf16x2 (hi = truncated high bits, lo = residual).
__device__ __forceinline__ void split2(float x0, float x1, uint32_t& hi, uint32_t& lo)
{
    uint32_t u0 = __float_as_uint(x0) & 0xFFFF0000u;
    uint32_t u1 = __float_as_uint(x1) & 0xFFFF0000u;
    hi = __byte_perm(u0, u1, 0x7632);      // low half = bf(x0), high = bf(x1)
    float l0 = x0 - __uint_as_float(u0);
    float l1 = x1 - __uint_as_float(u1);
    asm("cvt.rn.bf16x2.f32 %0, %1, %2;" : "=r"(lo) : "f"(l1), "f"(l0));
}

__device__ __forceinline__ void mma16816(float& d0, float& d1, float& d2, float& d3,
                                         uint32_t a0, uint32_t a1, uint32_t a2, uint32_t a3,
                                         uint32_t b0, uint32_t b1)
{
    asm volatile(
        "mma.sync.aligned.m16n8k16.row.col.f32.bf16.bf16.f32 "
        "{%0,%1,%2,%3}, {%4,%5,%6,%7}, {%8,%9}, {%0,%1,%2,%3};"
        : "+f"(d0), "+f"(d1), "+f"(d2), "+f"(d3)
        : "r"(a0), "r"(a1), "r"(a2), "r"(a3), "r"(b0), "r"(b1));
}

// ---------------------------------------------------------------------------
__global__ void detect_idx_kernel(const unsigned int* __restrict__ adj_words, int n_edges)
{
    int i = threadIdx.x;
    int samples = n_edges < 1024 ? n_edges : 1024;
    int ok = 1;
    if (i < samples) ok = (adj_words[2 * i + 1] == 0u) ? 1 : 0;
    int all = __syncthreads_and(ok);
    if (i == 0) g_idx64 = all;
}

__device__ __forceinline__ int load_row(const void* adj, int e, int is64) {
    return is64 ? (int)__ldg((const long long*)adj + e)
                : __ldg((const int*)adj + e);
}
__device__ __forceinline__ int load_col(const void* adj, int e, int n_edges, int is64) {
    return is64 ? (int)__ldg((const long long*)adj + (size_t)n_edges + e)
                : __ldg((const int*)adj + (size_t)n_edges + e);
}

// ---------------------------------------------------------------------------
__global__ void zero_counts_kernel(int n)
{
    int i = blockIdx.x * blockDim.x + threadIdx.x;
    if (i < n) { g_rowcnt[i] = 0; g_rowfill[i] = 0; }
}

__global__ __launch_bounds__(256) void histogram_kernel(
    const void* __restrict__ adj, int n_edges)
{
    int e = blockIdx.x * blockDim.x + threadIdx.x;
    if (e >= n_edges) return;
    int r = load_row(adj, e, g_idx64);
    atomicAdd(&g_rowcnt[r], 1);
}

__device__ __forceinline__ int block_excl_scan(int v, int* warp_sums, int nwarps)
{
    const int lane = threadIdx.x & 31, w = threadIdx.x >> 5;
    int x = v;
    #pragma unroll
    for (int off = 1; off < 32; off <<= 1) {
        int y = __shfl_up_sync(0xffffffffu, x, off);
        if (lane >= off) x += y;
    }
    if (lane == 31) warp_sums[w] = x;
    __syncthreads();
    if (w == 0) {
        int s = (lane < nwarps) ? warp_sums[lane] : 0;
        #pragma unroll
        for (int off = 1; off < 32; off <<= 1) {
            int y = __shfl_up_sync(0xffffffffu, s, off);
            if (lane >= off) s += y;
        }
        if (lane < nwarps) warp_sums[lane] = s;
    }
    __syncthreads();
    int base = (w > 0) ? warp_sums[w - 1] : 0;
    return base + x - v;
}

__global__ __launch_bounds__(1024) void scan1_kernel(int n)
{
    __shared__ int ws[32];
    int i = blockIdx.x * 1024 + threadIdx.x;
    int v = (i < n) ? g_rowcnt[i] : 0;
    int ex = block_excl_scan(v, ws, 32);
    if (threadIdx.x == 1023) g_blocksum[blockIdx.x] = ex + v;
}

__global__ __launch_bounds__(256) void scan2_kernel(int nb)
{
    __shared__ int ws[32];
    int i = threadIdx.x;
    int v = (i < nb) ? g_blocksum[i] : 0;
    int ex = block_excl_scan(v, ws, 8);
    if (i < nb) g_blockoff[i] = ex;
}

__global__ __launch_bounds__(1024) void scan3_kernel(int n)
{
    __shared__ int ws[32];
    int i = blockIdx.x * 1024 + threadIdx.x;
    int v = (i < n) ? g_rowcnt[i] : 0;
    int ex = block_excl_scan(v, ws, 32);
    int base = g_blockoff[blockIdx.x];
    if (i < n)      g_rowptr[i] = base + ex;
    if (i == n - 1) g_rowptr[n] = base + ex + v;
}

__global__ __launch_bounds__(256) void scatter_kernel(
    const void* __restrict__ adj, const float* __restrict__ vals, int n_edges)
{
    int e = blockIdx.x * blockDim.x + threadIdx.x;
    if (e >= n_edges) return;
    const int is64 = g_idx64;
    int r = load_row(adj, e, is64);
    int c = load_col(adj, e, n_edges, is64);
    float v = __ldg(vals + e);
    int pos = g_rowptr[r] + atomicAdd(&g_rowfill[r], 1);
    g_csr[pos] = make_int2(c, __float_as_int(v));
}

// ---------------------------------------------------------------------------
// GEMM1 via mma.sync bf16 split (hh + hl + lh): XW1 = feature @ W1.
// Persistent blocks (512 thr = 16 warps); W1^T split tiles staged in smem
// once per block; each warp computes a 16-row x 16-col tile per iteration,
// loading A fragments straight from gmem (full 32B sector utilization).
__global__ __launch_bounds__(512) void gemm1_mma_kernel(
    const float* __restrict__ feature,
    const float* __restrict__ W1,
    int n_nodes, int ntiles256)
{
    extern __shared__ char smem[];
    uint32_t* shi = (uint32_t*)smem;                    // [16][KPW] packed bf16x2
    uint32_t* slo = (uint32_t*)(smem + SMEM_BHALF);

    const int tid  = threadIdx.x;
    const int warp = tid >> 5;
    const int lane = tid & 31;
    const int g    = lane >> 2;     // fragment row group 0..7
    const int q2   = (lane & 3) * 2;

    // --- stage W1^T split (zero-padded to KP) ---
    for (int idx = tid; idx < 16 * KPW; idx += 512) {
        int n  = idx / KPW;
        int kp = idx - n * KPW;
        int k  = kp * 2;
        float w0 = (k     < IN_DIM) ? __ldg(W1 + (size_t)k       * HID + n) : 0.0f;
        float w1 = (k + 1 < IN_DIM) ? __ldg(W1 + (size_t)(k + 1) * HID + n) : 0.0f;
        uint32_t hi, lo;
        split2(w0, w1, hi, lo);
        shi[n * KPW + kp] = hi;
        slo[n * KPW + kp] = lo;
    }
    __syncthreads();

    // B-fragment smem word indices for this thread (per n8 half)
    const int bw0 = g * KPW + (lane & 3);          // half 0, k-offset base
    const int bw1 = (8 + g) * KPW + (lane & 3);    // half 1

    for (int t = blockIdx.x; t < ntiles256; t += gridDim.x) {
        const int row0 = t * 256 + warp * 16;
        const int rg0  = row0 + g;          // this thread's row (group 0)
        const int rg1  = rg0 + 8;           // row (group 1)
        const bool full = (row0 + 15 < n_nodes);

        float d[2][4];
        #pragma unroll
        for (int h = 0; h < 2; h++)
            #pragma unroll
            for (int j = 0; j < 4; j++) d[h][j] = 0.0f;

        const float* p0 = feature + (size_t)rg0 * IN_DIM + q2;
        const float* p1 = feature + (size_t)rg1 * IN_DIM + q2;

        if (full) {
            #pragma unroll 2
            for (int s = 0; s < KSTEPS_FULL; s++) {
                const int k0 = s * 16;
                // A: 8 scalar LDGs (quad covers a full 32B sector each)
                float f00 = __ldg(p0 + k0),     f01 = __ldg(p0 + k0 + 1);
                float f02 = __ldg(p0 + k0 + 8), f03 = __ldg(p0 + k0 + 9);
                float f10 = __ldg(p1 + k0),     f11 = __ldg(p1 + k0 + 1);
                float f12 = __ldg(p1 + k0 + 8), f13 = __ldg(p1 + k0 + 9);
                uint32_t a0h, a0l, a1h, a1l, a2h, a2l, a3h, a3l;
                split2(f00, f01, a0h, a0l);
                split2(f02, f03, a2h, a2l);
                split2(f10, f11, a1h, a1l);
                split2(f12, f13, a3h, a3l);
                const int kw = k0 >> 1;
                #pragma unroll
                for (int h = 0; h < 2; h++) {
                    const int base = (h ? bw1 : bw0) + kw;
                    const uint32_t b0h = shi[base], b1h = shi[base + 4];
                    const uint32_t b0l = slo[base], b1l = slo[base + 4];
                    mma16816(d[h][0], d[h][1], d[h][2], d[h][3],
                             a0h, a1h, a2h, a3h, b0h, b1h);
                    mma16816(d[h][0], d[h][1], d[h][2], d[h][3],
                             a0h, a1h, a2h, a3h, b0l, b1l);
                    mma16816(d[h][0], d[h][1], d[h][2], d[h][3],
                             a0l, a1l, a2l, a3l, b0h, b1h);
                }
            }
            {   // k tail: k0 = 1424, cols 1424..1439 (valid < 1433)
                const int k0 = KSTEPS_FULL * 16;
                float f00 = (k0 + q2     < IN_DIM) ? __ldg(p0 + k0)     : 0.0f;
                float f01 = (k0 + q2 + 1 < IN_DIM) ? __ldg(p0 + k0 + 1) : 0.0f;
                float f02 = (k0 + q2 + 8 < IN_DIM) ? __ldg(p0 + k0 + 8) : 0.0f;
                float f03 = (k0 + q2 + 9 < IN_DIM) ? __ldg(p0 + k0 + 9) : 0.0f;
                float f10 = (k0 + q2     < IN_DIM) ? __ldg(p1 + k0)     : 0.0f;
                float f11 = (k0 + q2 + 1 < IN_DIM) ? __ldg(p1 + k0 + 1) : 0.0f;
                float f12 = (k0 + q2 + 8 < IN_DIM) ? __ldg(p1 + k0 + 8) : 0.0f;
                float f13 = (k0 + q2 + 9 < IN_DIM) ? __ldg(p1 + k0 + 9) : 0.0f;
                uint32_t a0h, a0l, a1h, a1l, a2h, a2l, a3h, a3l;
                split2(f00, f01, a0h, a0l);
                split2(f02, f03, a2h, a2l);
                split2(f10, f11, a1h, a1l);
                split2(f12, f13, a3h, a3l);
                const int kw = k0 >> 1;
                #pragma unroll
                for (int h = 0; h < 2; h++) {
                    const int base = (h ? bw1 : bw0) + kw;
                    const uint32_t b0h = shi[base], b1h = shi[base + 4];
                    const uint32_t b0l = slo[base], b1l = slo[base + 4];
                    mma16816(d[h][0], d[h][1], d[h][2], d[h][3],
                             a0h, a1h, a2h, a3h, b0h, b1h);
                    mma16816(d[h][0], d[h][1], d[h][2], d[h][3],
                             a0h, a1h, a2h, a3h, b0l, b1l);
                    mma16816(d[h][0], d[h][1], d[h][2], d[h][3],
                             a0l, a1l, a2l, a3l, b0h, b1h);
                }
            }
        } else {
            // Edge tile: every load predicated on row and k bounds.
            const bool r0ok = (rg0 < n_nodes), r1ok = (rg1 < n_nodes);
            for (int s = 0; s < KSTEPS_FULL + 1; s++) {
                const int k0 = s * 16;
                const bool kv0 = (k0 + q2     < IN_DIM);
                const bool kv1 = (k0 + q2 + 1 < IN_DIM);
                const bool kv2 = (k0 + q2 + 8 < IN_DIM);
                const bool kv3 = (k0 + q2 + 9 < IN_DIM);
                float f00 = (r0ok && kv0) ? __ldg(p0 + k0)     : 0.0f;
                float f01 = (r0ok && kv1) ? __ldg(p0 + k0 + 1) : 0.0f;
                float f02 = (r0ok && kv2) ? __ldg(p0 + k0 + 8) : 0.0f;
                float f03 = (r0ok && kv3) ? __ldg(p0 + k0 + 9) : 0.0f;
                float f10 = (r1ok && kv0) ? __ldg(p1 + k0)     : 0.0f;
                float f11 = (r1ok && kv1) ? __ldg(p1 + k0 + 1) : 0.0f;
                float f12 = (r1ok && kv2) ? __ldg(p1 + k0 + 8) : 0.0f;
                float f13 = (r1ok && kv3) ? __ldg(p1 + k0 + 9) : 0.0f;
                uint32_t a0h, a0l, a1h, a1l, a2h, a2l, a3h, a3l;
                split2(f00, f01, a0h, a0l);
                split2(f02, f03, a2h, a2l);
                split2(f10, f11, a1h, a1l);
                split2(f12, f13, a3h, a3l);
                const int kw = k0 >> 1;
                #pragma unroll
                for (int h = 0; h < 2; h++) {
                    const int base = (h ? bw1 : bw0) + kw;
                    const uint32_t b0h = shi[base], b1h = shi[base + 4];
                    const uint32_t b0l = slo[base], b1l = slo[base + 4];
                    mma16816(d[h][0], d[h][1], d[h][2], d[h][3],
                             a0h, a1h, a2h, a3h, b0h, b1h);
                    mma16816(d[h][0], d[h][1], d[h][2], d[h][3],
                             a0h, a1h, a2h, a3h, b0l, b1l);
                    mma16816(d[h][0], d[h][1], d[h][2], d[h][3],
                             a0l, a1l, a2l, a3l, b0h, b1h);
                }
            }
        }

        // --- store D: row g gets d[h][0..1], row g+8 gets d[h][2..3] ---
        if (rg0 < n_nodes) {
            float* o = g_xw1 + (size_t)rg0 * HID;
            *(float2*)(o + q2)     = make_float2(d[0][0], d[0][1]);
            *(float2*)(o + 8 + q2) = make_float2(d[1][0], d[1][1]);
        }
        if (rg1 < n_nodes) {
            float* o = g_xw1 + (size_t)rg1 * HID;
            *(float2*)(o + q2)     = make_float2(d[0][2], d[0][3]);
            *(float2*)(o + 8 + q2) = make_float2(d[1][2], d[1][3]);
        }
    }
}

// ---------------------------------------------------------------------------
__global__ __launch_bounds__(256) void spmm1_gather_kernel(int n_nodes)
{
    const int warp_id = (blockIdx.x * blockDim.x + threadIdx.x) >> 5;
    if (warp_id >= n_nodes) return;
    const int lane = threadIdx.x & 31;
    const int g  = lane >> 2;
    const int j4 = lane & 3;

    const int start = g_rowptr[warp_id];
    const int end   = g_rowptr[warp_id + 1];

    float4 acc = make_float4(0.f, 0.f, 0.f, 0.f);
    for (int e = start + g; e < end; e += 8) {
        const int2 ev = __ldg(&g_csr[e]);
        const float v = __int_as_float(ev.y);
        const float4 x = __ldg((const float4*)(g_xw1 + (size_t)ev.x * HID) + j4);
        acc.x += v * x.x; acc.y += v * x.y; acc.z += v * x.z; acc.w += v * x.w;
    }
    #pragma unroll
    for (int off = 16; off >= 4; off >>= 1) {
        acc.x += __shfl_xor_sync(0xffffffffu, acc.x, off);
        acc.y += __shfl_xor_sync(0xffffffffu, acc.y, off);
        acc.z += __shfl_xor_sync(0xffffffffu, acc.z, off);
        acc.w += __shfl_xor_sync(0xffffffffu, acc.w, off);
    }
    if (g == 0)
        ((float4*)(g_h + (size_t)warp_id * HID))[j4] = acc;
}

// ---------------------------------------------------------------------------
__global__ __launch_bounds__(256) void gemm2_kernel(
    const float* __restrict__ b1,
    const float* __restrict__ W2,
    int n_nodes)
{
    __shared__ float sW2[HID * OUTD];
    __shared__ float sb1[HID];
    if (threadIdx.x < HID * OUTD) sW2[threadIdx.x] = W2[threadIdx.x];
    if (threadIdx.x < HID)        sb1[threadIdx.x] = b1[threadIdx.x];
    __syncthreads();

    int i = blockIdx.x * blockDim.x + threadIdx.x;
    if (i >= n_nodes) return;

    float h[HID];
    const float4* hp = (const float4*)(g_h + (size_t)i * HID);
    #pragma unroll
    for (int q = 0; q < 4; q++) {
        float4 a = hp[q];
        h[4 * q + 0] = a.x; h[4 * q + 1] = a.y;
        h[4 * q + 2] = a.z; h[4 * q + 3] = a.w;
    }

    float o[OUTD];
    #pragma unroll
    for (int j = 0; j < OUTD; j++) o[j] = 0.0f;
    #pragma unroll
    for (int k = 0; k < HID; k++) {
        const float hv = fmaxf(h[k] + sb1[k], 0.0f);
        #pragma unroll
        for (int j = 0; j < OUTD; j++) o[j] += hv * sW2[k * OUTD + j];
    }

    float4* gp = (float4*)(g_g + (size_t)i * 8);
    gp[0] = make_float4(o[0], o[1], o[2], o[3]);
    gp[1] = make_float4(o[4], o[5], o[6], 0.0f);
}

// ---------------------------------------------------------------------------
__global__ __launch_bounds__(256) void spmm2_gather_kernel(
    float* __restrict__ out, const float* __restrict__ b2, int n_nodes)
{
    const int warp_id = (blockIdx.x * blockDim.x + threadIdx.x) >> 5;
    if (warp_id >= n_nodes) return;
    const int lane = threadIdx.x & 31;
    const int g  = lane >> 1;
    const int j4 = lane & 1;

    const int start = g_rowptr[warp_id];
    const int end   = g_rowptr[warp_id + 1];

    float4 acc = make_float4(0.f, 0.f, 0.f, 0.f);
    for (int e = start + g; e < end; e += 16) {
        const int2 ev = __ldg(&g_csr[e]);
        const float v = __int_as_float(ev.y);
        const float4 x = __ldg((const float4*)(g_g + (size_t)ev.x * 8) + j4);
        acc.x += v * x.x; acc.y += v * x.y; acc.z += v * x.z; acc.w += v * x.w;
    }
    #pragma unroll
    for (int off = 16; off >= 2; off >>= 1) {
        acc.x += __shfl_xor_sync(0xffffffffu, acc.x, off);
        acc.y += __shfl_xor_sync(0xffffffffu, acc.y, off);
        acc.z += __shfl_xor_sync(0xffffffffu, acc.z, off);
        acc.w += __shfl_xor_sync(0xffffffffu, acc.w, off);
    }
    float* o = out + (size_t)warp_id * OUTD;
    if (lane == 0) {
        o[0] = acc.x + __ldg(b2 + 0);
        o[1] = acc.y + __ldg(b2 + 1);
        o[2] = acc.z + __ldg(b2 + 2);
        o[3] = acc.w + __ldg(b2 + 3);
    } else if (lane == 1) {
        o[4] = acc.x + __ldg(b2 + 4);
        o[5] = acc.y + __ldg(b2 + 5);
        o[6] = acc.z + __ldg(b2 + 6);
    }
}

// ---------------------------------------------------------------------------
extern "C" void kernel_launch(void* const* d_in, const int* in_sizes, int n_in,
                              void* d_out, int out_size)
{
    const void*  adj     = d_in[0];
    const float* vals    = (const float*)d_in[1];
    const float* feature = (const float*)d_in[2];
    const float* W1      = (const float*)d_in[3];
    const float* b1      = (const float*)d_in[4];
    const float* W2      = (const float*)d_in[5];
    const float* b2      = (const float*)d_in[6];
    float*       out     = (float*)d_out;

    const int n_edges   = in_sizes[1];
    const int n_nodes   = in_sizes[2] / IN_DIM;
    const int ntiles256 = (n_nodes + 255) / 256;
    const int nb        = (n_nodes + 1023) / 1024;

    static cudaStream_t s2 = nullptr;
    static cudaEvent_t ev_fork = nullptr, ev_join = nullptr;
    static int n_sms = 148;
    if (!s2) {
        cudaFuncSetAttribute(gemm1_mma_kernel,
                             cudaFuncAttributeMaxDynamicSharedMemorySize, SMEM_B_BYTES);
        cudaStreamCreateWithFlags(&s2, cudaStreamNonBlocking);
        cudaEventCreateWithFlags(&ev_fork, cudaEventDisableTiming);
        cudaEventCreateWithFlags(&ev_join, cudaEventDisableTiming);
        int dev = 0;
        cudaGetDevice(&dev);
        cudaDeviceGetAttribute(&n_sms, cudaDevAttrMultiProcessorCount, dev);
    }

    cudaEventRecord(ev_fork, 0);
    cudaStreamWaitEvent(s2, ev_fork, 0);

    // CSR chain on side stream; gemm1 stays the 4th launch (profiled slot).
    detect_idx_kernel<<<1, 1024, 0, s2>>>((const unsigned int*)adj, n_edges);
    zero_counts_kernel<<<nb, 1024, 0, s2>>>(n_nodes);
    histogram_kernel<<<(n_edges + 255) / 256, 256, 0, s2>>>(adj, n_edges);

    gemm1_mma_kernel<<<2 * n_sms, 512, SMEM_B_BYTES>>>(feature, W1, n_nodes, ntiles256);

    scan1_kernel<<<nb, 1024, 0, s2>>>(n_nodes);
    scan2_kernel<<<1, 256, 0, s2>>>(nb);
    scan3_kernel<<<nb, 1024, 0, s2>>>(n_nodes);
    scatter_kernel<<<(n_edges + 255) / 256, 256, 0, s2>>>(adj, vals, n_edges);
    cudaEventRecord(ev_join, s2);

    cudaStreamWaitEvent(0, ev_join, 0);
    spmm1_gather_kernel<<<(n_nodes * 32 + 255) / 256, 256>>>(n_nodes);
    gemm2_kernel<<<(n_nodes + 255) / 256, 256>>>(b1, W2, n_nodes);
    spmm2_gather_kernel<<<(n_nodes * 32 + 255) / 256, 256>>>(out, b2, n_nodes);
}